// round 1
// baseline (speedup 1.0000x reference)
#include <cuda_runtime.h>
#include <math.h>

#define N 8192
#define D 128

// ---------------- scratch (device globals: no allocation allowed) ----------
__device__ float g_centers[(size_t)N * D];
__device__ float g_c2[N];
__device__ float g_x2[N];
__device__ int   g_negIdx[N];
__device__ float g_loss[N];

// ---------------------------------------------------------------------------
// Kernel 1: centers[i,:] = (sum_j mask[i,j] * X[j,:]) / count[i]
// Block tile: 64 anchor rows x 128 dims, loop j in chunks of 32.
// Thread tile: 4 rows x 8 cols (256 threads as 16x16).
// ---------------------------------------------------------------------------
#define A_BM 64
#define A_BK 32

__global__ __launch_bounds__(256) void centers_kernel(const float* __restrict__ X,
                                                      const int* __restrict__ S) {
    __shared__ float mS[A_BK][A_BM];   // transposed mask tile (k-major)
    __shared__ float xS[A_BK][D];      // inputs tile (k-major)

    const int tid = threadIdx.x;
    const int tx = tid & 15;           // 16 col-groups of 8
    const int ty = tid >> 4;           // 16 row-groups of 4
    const int rowBase = blockIdx.x * A_BM;

    float acc[4][8];
    float cnt[4];
#pragma unroll
    for (int r = 0; r < 4; r++) {
        cnt[r] = 0.f;
#pragma unroll
        for (int c = 0; c < 8; c++) acc[r][c] = 0.f;
    }

    for (int jb = 0; jb < N; jb += A_BK) {
        // load mask tile (64 rows x 32 j), transposed into mS[k][row]
        {
            int r  = tid >> 2;          // 0..63
            int k0 = (tid & 3) * 8;     // 0,8,16,24
            const int4* p = reinterpret_cast<const int4*>(S + (size_t)(rowBase + r) * N + jb + k0);
#pragma unroll
            for (int v = 0; v < 2; v++) {
                int4 m = p[v];
                int k = k0 + v * 4;
                mS[k + 0][r] = m.x ? 1.f : 0.f;
                mS[k + 1][r] = m.y ? 1.f : 0.f;
                mS[k + 2][r] = m.z ? 1.f : 0.f;
                mS[k + 3][r] = m.w ? 1.f : 0.f;
            }
        }
        // load inputs tile (32 j x 128 d), already k-major
        {
            int k  = tid >> 3;          // 0..31
            int c0 = (tid & 7) * 16;
            const float4* p = reinterpret_cast<const float4*>(X + (size_t)(jb + k) * D + c0);
            float4* q = reinterpret_cast<float4*>(&xS[k][c0]);
#pragma unroll
            for (int v = 0; v < 4; v++) q[v] = p[v];
        }
        __syncthreads();

#pragma unroll
        for (int kk = 0; kk < A_BK; kk++) {
            float4 m4 = *reinterpret_cast<const float4*>(&mS[kk][ty * 4]);
            float mr[4] = {m4.x, m4.y, m4.z, m4.w};
            float4 xa = *reinterpret_cast<const float4*>(&xS[kk][tx * 8]);
            float4 xb = *reinterpret_cast<const float4*>(&xS[kk][tx * 8 + 4]);
            float xr[8] = {xa.x, xa.y, xa.z, xa.w, xb.x, xb.y, xb.z, xb.w};
#pragma unroll
            for (int r = 0; r < 4; r++) {
                cnt[r] += mr[r];
#pragma unroll
                for (int c = 0; c < 8; c++) acc[r][c] += mr[r] * xr[c];
            }
        }
        __syncthreads();
    }

#pragma unroll
    for (int r = 0; r < 4; r++) {
        float inv = 1.0f / cnt[r];
        float* dst = g_centers + (size_t)(rowBase + ty * 4 + r) * D + tx * 8;
#pragma unroll
        for (int c = 0; c < 8; c++) dst[c] = acc[r][c] * inv;
    }
}

// ---------------------------------------------------------------------------
// Kernel 2: squared norms of centers and inputs (warp per row)
// ---------------------------------------------------------------------------
__global__ __launch_bounds__(256) void norms_kernel(const float* __restrict__ X) {
    int warp = (blockIdx.x * blockDim.x + threadIdx.x) >> 5;
    int lane = threadIdx.x & 31;
    if (warp >= 2 * N) return;
    const float* src = (warp < N) ? (g_centers + (size_t)warp * D)
                                  : (X + (size_t)(warp - N) * D);
    float4 a = reinterpret_cast<const float4*>(src)[lane];
    float s = a.x * a.x + a.y * a.y + a.z * a.z + a.w * a.w;
#pragma unroll
    for (int o = 16; o; o >>= 1) s += __shfl_xor_sync(0xffffffffu, s, o);
    if (lane == 0) {
        if (warp < N) g_c2[warp] = s;
        else          g_x2[warp - N] = s;
    }
}

// ---------------------------------------------------------------------------
// Kernel 3: hard-negative argmin. Block = 64 anchor rows, loops over ALL j
// in tiles of 128. Metric v = max(x2[j] - 2*dot, -c2[i]) == max(d2,0)-c2[i]
// (same ordering AND same ties as reference's sqrt(max(d2,0))); positives -> +inf.
// Dynamic smem: cS[128k][64rows] (32KB) + xS[128k][128j] (64KB) = 96KB.
// ---------------------------------------------------------------------------
#define B_BN 128

__global__ __launch_bounds__(256) void argmin_kernel(const float* __restrict__ X,
                                                     const int* __restrict__ S) {
    extern __shared__ float sm[];
    float* cS = sm;             // [128][64]
    float* xS = sm + 128 * 64;  // [128][128]
    __shared__ float redV[64][16];
    __shared__ int   redI[64][16];

    const int tid = threadIdx.x;
    const int tx = tid & 15;
    const int ty = tid >> 4;
    const int rowBase = blockIdx.x * 64;

    // preload centers tile transposed: cS[k][row]
    {
        int row = tid >> 2;
        int k0  = (tid & 3) * 32;
        const float4* p = reinterpret_cast<const float4*>(g_centers + (size_t)(rowBase + row) * D + k0);
#pragma unroll
        for (int v = 0; v < 8; v++) {
            float4 a = p[v];
            int k = k0 + v * 4;
            cS[(k + 0) * 64 + row] = a.x;
            cS[(k + 1) * 64 + row] = a.y;
            cS[(k + 2) * 64 + row] = a.z;
            cS[(k + 3) * 64 + row] = a.w;
        }
    }

    float negc2[4];
#pragma unroll
    for (int r = 0; r < 4; r++) negc2[r] = -g_c2[rowBase + ty * 4 + r];

    float best[4];
    int   bidx[4];
#pragma unroll
    for (int r = 0; r < 4; r++) { best[r] = 3.402823466e38f; bidx[r] = 0; }

    __syncthreads();

    for (int jb = 0; jb < N; jb += B_BN) {
        // load X tile transposed: xS[k][j]
        {
            int j  = tid >> 1;
            int k0 = (tid & 1) * 64;
            const float4* p = reinterpret_cast<const float4*>(X + (size_t)(jb + j) * D + k0);
#pragma unroll
            for (int v = 0; v < 16; v++) {
                float4 a = p[v];
                int k = k0 + v * 4;
                xS[(k + 0) * 128 + j] = a.x;
                xS[(k + 1) * 128 + j] = a.y;
                xS[(k + 2) * 128 + j] = a.z;
                xS[(k + 3) * 128 + j] = a.w;
            }
        }
        __syncthreads();

        float acc[4][8];
#pragma unroll
        for (int r = 0; r < 4; r++)
#pragma unroll
            for (int c = 0; c < 8; c++) acc[r][c] = 0.f;

#pragma unroll 4
        for (int kk = 0; kk < D; kk++) {
            float4 c4 = *reinterpret_cast<const float4*>(&cS[kk * 64 + ty * 4]);
            float cr[4] = {c4.x, c4.y, c4.z, c4.w};
            float4 xa = *reinterpret_cast<const float4*>(&xS[kk * 128 + tx * 8]);
            float4 xb = *reinterpret_cast<const float4*>(&xS[kk * 128 + tx * 8 + 4]);
            float xr[8] = {xa.x, xa.y, xa.z, xa.w, xb.x, xb.y, xb.z, xb.w};
#pragma unroll
            for (int r = 0; r < 4; r++)
#pragma unroll
                for (int c = 0; c < 8; c++) acc[r][c] += cr[r] * xr[c];
        }

        // epilogue: metric + mask + running argmin (ascending j order => first-min ties)
        float4 x2a = *reinterpret_cast<const float4*>(&g_x2[jb + tx * 8]);
        float4 x2b = *reinterpret_cast<const float4*>(&g_x2[jb + tx * 8 + 4]);
        float x2c[8] = {x2a.x, x2a.y, x2a.z, x2a.w, x2b.x, x2b.y, x2b.z, x2b.w};

#pragma unroll
        for (int r = 0; r < 4; r++) {
            const size_t srow = (size_t)(rowBase + ty * 4 + r) * N + jb + tx * 8;
            int4 m0 = *reinterpret_cast<const int4*>(S + srow);
            int4 m1 = *reinterpret_cast<const int4*>(S + srow + 4);
            int mm[8] = {m0.x, m0.y, m0.z, m0.w, m1.x, m1.y, m1.z, m1.w};
#pragma unroll
            for (int c = 0; c < 8; c++) {
                float v = fmaxf(x2c[c] - 2.f * acc[r][c], negc2[r]);
                if (mm[c]) v = 3.402823466e38f;
                if (v < best[r]) { best[r] = v; bidx[r] = jb + tx * 8 + c; }
            }
        }
        __syncthreads();
    }

    // reduce across the 16 tx threads per row (keep lowest j on ties)
#pragma unroll
    for (int r = 0; r < 4; r++) {
        redV[ty * 4 + r][tx] = best[r];
        redI[ty * 4 + r][tx] = bidx[r];
    }
    __syncthreads();
    if (tid < 64) {
        float bv = redV[tid][0];
        int   bi = redI[tid][0];
#pragma unroll
        for (int t = 1; t < 16; t++) {
            float v = redV[tid][t];
            int   i = redI[tid][t];
            if (v < bv || (v == bv && i < bi)) { bv = v; bi = i; }
        }
        g_negIdx[rowBase + tid] = bi;
    }
}

// ---------------------------------------------------------------------------
// Kernel 4: per-anchor triplet loss term (warp per anchor).
// NOTE the reference adds EPS to EACH COMPONENT before the norm.
// ---------------------------------------------------------------------------
__global__ __launch_bounds__(128) void loss_kernel(const float* __restrict__ X) {
    int a = blockIdx.x * 4 + (threadIdx.x >> 5);
    int lane = threadIdx.x & 31;
    const float* c  = g_centers + (size_t)a * D;
    const float* x  = X + (size_t)a * D;
    const float* nx = X + (size_t)g_negIdx[a] * D;
    float4 cv = reinterpret_cast<const float4*>(c)[lane];
    float4 xv = reinterpret_cast<const float4*>(x)[lane];
    float4 nv = reinterpret_cast<const float4*>(nx)[lane];
    const float EPS = 1e-6f;
    float t, sap = 0.f, san = 0.f;
    t = cv.x - xv.x + EPS; sap += t * t;
    t = cv.y - xv.y + EPS; sap += t * t;
    t = cv.z - xv.z + EPS; sap += t * t;
    t = cv.w - xv.w + EPS; sap += t * t;
    t = cv.x - nv.x + EPS; san += t * t;
    t = cv.y - nv.y + EPS; san += t * t;
    t = cv.z - nv.z + EPS; san += t * t;
    t = cv.w - nv.w + EPS; san += t * t;
#pragma unroll
    for (int o = 16; o; o >>= 1) {
        sap += __shfl_xor_sync(0xffffffffu, sap, o);
        san += __shfl_xor_sync(0xffffffffu, san, o);
    }
    if (lane == 0)
        g_loss[a] = fmaxf(sqrtf(sap) - sqrtf(san) + 0.3f, 0.f);
}

// ---------------------------------------------------------------------------
// Kernel 5: mean reduction -> out[0]
// ---------------------------------------------------------------------------
__global__ __launch_bounds__(1024) void reduce_kernel(float* out) {
    __shared__ float smr[1024];
    float s = 0.f;
    for (int i = threadIdx.x; i < N; i += 1024) s += g_loss[i];
    smr[threadIdx.x] = s;
    __syncthreads();
    for (int o = 512; o; o >>= 1) {
        if (threadIdx.x < o) smr[threadIdx.x] += smr[threadIdx.x + o];
        __syncthreads();
    }
    if (threadIdx.x == 0) out[0] = smr[0] * (1.0f / N);
}

// ---------------------------------------------------------------------------
extern "C" void kernel_launch(void* const* d_in, const int* in_sizes, int n_in,
                              void* d_out, int out_size) {
    const float* X;
    const int* S;
    if (in_sizes[0] == N * D) {
        X = (const float*)d_in[0];
        S = (const int*)d_in[1];
    } else {
        X = (const float*)d_in[1];
        S = (const int*)d_in[0];
    }

    cudaFuncSetAttribute(argmin_kernel, cudaFuncAttributeMaxDynamicSharedMemorySize, 96 * 1024);

    centers_kernel<<<N / A_BM, 256>>>(X, S);
    norms_kernel<<<(2 * N * 32) / 256, 256>>>(X);
    argmin_kernel<<<N / 64, 256, 96 * 1024>>>(X, S);
    loss_kernel<<<N / 4, 128>>>(X);
    reduce_kernel<<<1, 1024>>>((float*)d_out);
}

// round 3
// speedup vs baseline: 4.7221x; 4.7221x over previous
#include <cuda_runtime.h>
#include <cuda_bf16.h>
#include <math.h>
#include <stdint.h>

#define NN 8192
#define DD 128
#define FLTMAX 3.402823466e38f
#define STRIDE 136   // padded bf16 row stride (272B): conflict-free frag loads

// ---------------- device-global scratch (no runtime allocation) -------------
__device__ float          g_centers[(size_t)NN * DD];
__device__ __nv_bfloat16  g_centersB[(size_t)NN * DD];
__device__ __nv_bfloat16  g_Xb [(size_t)NN * DD];   // X bf16 row-major [j][d]
__device__ __nv_bfloat16  g_XbT[(size_t)DD * NN];   // X^T bf16 [d][j]
__device__ float          g_x2[NN];
__device__ float          g_c2[NN];
__device__ float          g_part[(size_t)2 * NN * DD];
__device__ float          g_cntPart[2 * NN];
__device__ float          g_blockBest[(size_t)64 * NN];
__device__ int            g_blockIdx [(size_t)64 * NN];
__device__ int            g_negIdx[NN];
__device__ float          g_loss[NN];

// ---------------- HMMA helper ------------------------------------------------
__device__ __forceinline__ void mma16816(float c[4],
                                         uint32_t a0, uint32_t a1, uint32_t a2, uint32_t a3,
                                         uint32_t b0, uint32_t b1) {
    asm volatile(
        "mma.sync.aligned.m16n8k16.row.col.f32.bf16.bf16.f32 "
        "{%0,%1,%2,%3}, {%4,%5,%6,%7}, {%8,%9}, {%0,%1,%2,%3};"
        : "+f"(c[0]), "+f"(c[1]), "+f"(c[2]), "+f"(c[3])
        : "r"(a0), "r"(a1), "r"(a2), "r"(a3), "r"(b0), "r"(b1));
}

__device__ __forceinline__ uint32_t lds32(const __nv_bfloat16* p) {
    return *reinterpret_cast<const uint32_t*>(p);
}

// ---------------------------------------------------------------------------
// prep: Xb (bf16), XbT (bf16 transposed) via smem tile transpose
// ---------------------------------------------------------------------------
__global__ __launch_bounds__(256) void prep_kernel(const float* __restrict__ X) {
    __shared__ float tile[32][33];
    int tx = threadIdx.x & 31, ty = threadIdx.x >> 5;
    int j0 = blockIdx.x * 32, d0 = blockIdx.y * 32;
#pragma unroll
    for (int jr = ty; jr < 32; jr += 8) {
        float v = X[(size_t)(j0 + jr) * DD + d0 + tx];
        tile[jr][tx] = v;
        g_Xb[(size_t)(j0 + jr) * DD + d0 + tx] = __float2bfloat16_rn(v);
    }
    __syncthreads();
#pragma unroll
    for (int dr = ty; dr < 32; dr += 8)
        g_XbT[(size_t)(d0 + dr) * NN + j0 + tx] = __float2bfloat16_rn(tile[tx][dr]);
}

__global__ __launch_bounds__(256) void x2_kernel(const float* __restrict__ X) {
    int warp = blockIdx.x * 8 + (threadIdx.x >> 5);
    int lane = threadIdx.x & 31;
    float4 a = reinterpret_cast<const float4*>(X + (size_t)warp * DD)[lane];
    float s = a.x * a.x + a.y * a.y + a.z * a.z + a.w * a.w;
#pragma unroll
    for (int o = 16; o; o >>= 1) s += __shfl_xor_sync(0xffffffffu, s, o);
    if (lane == 0) g_x2[warp] = s;
}

// ---------------------------------------------------------------------------
// centers HMMA: part[128 rows, 128 dims] = mask_bf16 @ XbT over K-split 4096
// grid (64 mb, 2 split), 256 threads (8 warps as 2x4). A=mask, B=XbT.
// smem: As[128][136] bf16 + Bs[128][136] bf16 = 69632 B
// ---------------------------------------------------------------------------
__global__ __launch_bounds__(256) void centers_mma(const int* __restrict__ S) {
    extern __shared__ __align__(16) char sm[];
    __nv_bfloat16* As = reinterpret_cast<__nv_bfloat16*>(sm);
    __nv_bfloat16* Bs = reinterpret_cast<__nv_bfloat16*>(sm + 34816);

    const int tid = threadIdx.x;
    const int wid = tid >> 5, lane = tid & 31;
    const int wm = wid >> 2, wn = wid & 3;          // 2 x 4 warps
    const int g = lane >> 2, tig = lane & 3;
    const int rowBase = blockIdx.x * 128;
    const int split = blockIdx.y;
    const int kBase = split * 4096;

    const int lr = tid >> 1;          // load row 0..127
    const int half = tid & 1;         // 64-elem half

    float acc[4][4][4];
#pragma unroll
    for (int mt = 0; mt < 4; mt++)
#pragma unroll
        for (int nt = 0; nt < 4; nt++)
#pragma unroll
            for (int q = 0; q < 4; q++) acc[mt][nt][q] = 0.f;
    int cnt = 0;

    for (int it = 0; it < 32; it++) {
        const int k0 = kBase + it * 128;
        // A: mask row lr, 64 ints -> 64 bf16
        {
            const int4* src = reinterpret_cast<const int4*>(S + (size_t)(rowBase + lr) * NN + k0 + half * 64);
            uint4* dst = reinterpret_cast<uint4*>(As + lr * STRIDE + half * 64);
#pragma unroll
            for (int u = 0; u < 8; u++) {
                int4 q0 = src[2 * u], q1 = src[2 * u + 1];
                cnt += (q0.x != 0) + (q0.y != 0) + (q0.z != 0) + (q0.w != 0)
                     + (q1.x != 0) + (q1.y != 0) + (q1.z != 0) + (q1.w != 0);
                uint4 v;
                v.x = (q0.x ? 0x3F80u : 0u) | ((q0.y ? 0x3F80u : 0u) << 16);
                v.y = (q0.z ? 0x3F80u : 0u) | ((q0.w ? 0x3F80u : 0u) << 16);
                v.z = (q1.x ? 0x3F80u : 0u) | ((q1.y ? 0x3F80u : 0u) << 16);
                v.w = (q1.z ? 0x3F80u : 0u) | ((q1.w ? 0x3F80u : 0u) << 16);
                dst[u] = v;
            }
        }
        // B: XbT row (dim) lr, 64 bf16
        {
            const uint4* src = reinterpret_cast<const uint4*>(g_XbT + (size_t)lr * NN + k0 + half * 64);
            uint4* dst = reinterpret_cast<uint4*>(Bs + lr * STRIDE + half * 64);
#pragma unroll
            for (int u = 0; u < 8; u++) dst[u] = src[u];
        }
        __syncthreads();

#pragma unroll
        for (int ks = 0; ks < 8; ks++) {
            const int kk = ks * 16;
            uint32_t a[4][4], b[4][2];
#pragma unroll
            for (int mt = 0; mt < 4; mt++) {
                const __nv_bfloat16* p = As + (wm * 64 + mt * 16 + g) * STRIDE + kk + tig * 2;
                a[mt][0] = lds32(p);
                a[mt][1] = lds32(p + 8 * STRIDE);
                a[mt][2] = lds32(p + 8);
                a[mt][3] = lds32(p + 8 * STRIDE + 8);
            }
#pragma unroll
            for (int nt = 0; nt < 4; nt++) {
                const __nv_bfloat16* p = Bs + (wn * 32 + nt * 8 + g) * STRIDE + kk + tig * 2;
                b[nt][0] = lds32(p);
                b[nt][1] = lds32(p + 8);
            }
#pragma unroll
            for (int mt = 0; mt < 4; mt++)
#pragma unroll
                for (int nt = 0; nt < 4; nt++)
                    mma16816(acc[mt][nt], a[mt][0], a[mt][1], a[mt][2], a[mt][3],
                             b[nt][0], b[nt][1]);
        }
        __syncthreads();
    }

    // epilogue: raw partial sums
#pragma unroll
    for (int mt = 0; mt < 4; mt++)
#pragma unroll
        for (int h = 0; h < 2; h++) {
            int grow = rowBase + wm * 64 + mt * 16 + h * 8 + g;
#pragma unroll
            for (int nt = 0; nt < 4; nt++) {
                int col = wn * 32 + nt * 8 + tig * 2;
                float2 v = make_float2(acc[mt][nt][h * 2], acc[mt][nt][h * 2 + 1]);
                *reinterpret_cast<float2*>(g_part + ((size_t)split * NN + grow) * DD + col) = v;
            }
        }
    // counts: combine the two half-threads of each row
    int other = __shfl_xor_sync(0xffffffffu, cnt, 1);
    if (half == 0) g_cntPart[split * NN + rowBase + lr] = (float)(cnt + other);
}

// ---------------------------------------------------------------------------
// centers combine: sum 2 split partials, /count, write fp32 + bf16 + c2
// ---------------------------------------------------------------------------
__global__ __launch_bounds__(128) void centers_combine() {
    int row = blockIdx.x * 4 + (threadIdx.x >> 5);
    int lane = threadIdx.x & 31;
    float cnt = g_cntPart[row] + g_cntPart[NN + row];
    float inv = 1.0f / cnt;
    float4 p0 = reinterpret_cast<const float4*>(g_part + (size_t)row * DD)[lane];
    float4 p1 = reinterpret_cast<const float4*>(g_part + ((size_t)NN + row) * DD)[lane];
    float4 s = make_float4((p0.x + p1.x) * inv, (p0.y + p1.y) * inv,
                           (p0.z + p1.z) * inv, (p0.w + p1.w) * inv);
    reinterpret_cast<float4*>(g_centers + (size_t)row * DD)[lane] = s;
    __nv_bfloat162 lo = __floats2bfloat162_rn(s.x, s.y);
    __nv_bfloat162 hi = __floats2bfloat162_rn(s.z, s.w);
    uint2 packed = make_uint2(*reinterpret_cast<uint32_t*>(&lo), *reinterpret_cast<uint32_t*>(&hi));
    reinterpret_cast<uint2*>(g_centersB + (size_t)row * DD)[lane] = packed;
    float c2 = s.x * s.x + s.y * s.y + s.z * s.z + s.w * s.w;
#pragma unroll
    for (int o = 16; o; o >>= 1) c2 += __shfl_xor_sync(0xffffffffu, c2, o);
    if (lane == 0) g_c2[row] = c2;
}

// ---------------------------------------------------------------------------
// argmin HMMA: dot[128 rows, 128 j] = centersB @ Xb^T (K=128), fused argmin
// grid (64 nb, 64 mb), 256 threads (8 warps as 2x4).
// smem: As 34816 + Bs 34816 + x2s 512 + c2s 512 + redV 2048 + redI 2048
// ---------------------------------------------------------------------------
__global__ __launch_bounds__(256) void argmin_mma(const int* __restrict__ S) {
    extern __shared__ __align__(16) char sm[];
    __nv_bfloat16* As = reinterpret_cast<__nv_bfloat16*>(sm);
    __nv_bfloat16* Bs = reinterpret_cast<__nv_bfloat16*>(sm + 34816);
    float* x2s = reinterpret_cast<float*>(sm + 69632);
    float* c2s = x2s + 128;
    float* redV = c2s + 128;
    int*   redI = reinterpret_cast<int*>(redV + 512);

    const int tid = threadIdx.x;
    const int wid = tid >> 5, lane = tid & 31;
    const int wm = wid >> 2, wn = wid & 3;
    const int g = lane >> 2, tig = lane & 3;
    const int mBase = blockIdx.y * 128, jBase = blockIdx.x * 128;

    // loads
    {
        int lr = tid >> 1, half = tid & 1;
        const uint4* a = reinterpret_cast<const uint4*>(g_centersB + (size_t)(mBase + lr) * DD + half * 64);
        uint4* ad = reinterpret_cast<uint4*>(As + lr * STRIDE + half * 64);
        const uint4* b = reinterpret_cast<const uint4*>(g_Xb + (size_t)(jBase + lr) * DD + half * 64);
        uint4* bd = reinterpret_cast<uint4*>(Bs + lr * STRIDE + half * 64);
#pragma unroll
        for (int u = 0; u < 8; u++) { ad[u] = a[u]; bd[u] = b[u]; }
        if (tid < 32) reinterpret_cast<float4*>(x2s)[tid] = reinterpret_cast<const float4*>(g_x2 + jBase)[tid];
        else if (tid < 64) reinterpret_cast<float4*>(c2s)[tid - 32] = reinterpret_cast<const float4*>(g_c2 + mBase)[tid - 32];
    }
    __syncthreads();

    float acc[4][4][4];
#pragma unroll
    for (int mt = 0; mt < 4; mt++)
#pragma unroll
        for (int nt = 0; nt < 4; nt++)
#pragma unroll
            for (int q = 0; q < 4; q++) acc[mt][nt][q] = 0.f;

#pragma unroll
    for (int ks = 0; ks < 8; ks++) {
        const int kk = ks * 16;
        uint32_t a[4][4], b[4][2];
#pragma unroll
        for (int mt = 0; mt < 4; mt++) {
            const __nv_bfloat16* p = As + (wm * 64 + mt * 16 + g) * STRIDE + kk + tig * 2;
            a[mt][0] = lds32(p);
            a[mt][1] = lds32(p + 8 * STRIDE);
            a[mt][2] = lds32(p + 8);
            a[mt][3] = lds32(p + 8 * STRIDE + 8);
        }
#pragma unroll
        for (int nt = 0; nt < 4; nt++) {
            const __nv_bfloat16* p = Bs + (wn * 32 + nt * 8 + g) * STRIDE + kk + tig * 2;
            b[nt][0] = lds32(p);
            b[nt][1] = lds32(p + 8);
        }
#pragma unroll
        for (int mt = 0; mt < 4; mt++)
#pragma unroll
            for (int nt = 0; nt < 4; nt++)
                mma16816(acc[mt][nt], a[mt][0], a[mt][1], a[mt][2], a[mt][3],
                         b[nt][0], b[nt][1]);
    }

    // fused argmin epilogue: metric max(x2 - 2*dot, -c2), positives -> +inf
#pragma unroll
    for (int mt = 0; mt < 4; mt++)
#pragma unroll
        for (int h = 0; h < 2; h++) {
            int lrow = wm * 64 + mt * 16 + h * 8 + g;
            int grow = mBase + lrow;
            float negc2 = -c2s[lrow];
            float best = FLTMAX;
            int bidx = 0x7FFFFFFF;
#pragma unroll
            for (int nt = 0; nt < 4; nt++) {
                int lcol = wn * 32 + nt * 8 + tig * 2;
                int2 m = *reinterpret_cast<const int2*>(S + (size_t)grow * NN + jBase + lcol);
                float v0 = fmaxf(fmaf(-2.f, acc[mt][nt][h * 2 + 0], x2s[lcol + 0]), negc2);
                float v1 = fmaxf(fmaf(-2.f, acc[mt][nt][h * 2 + 1], x2s[lcol + 1]), negc2);
                if (m.x) v0 = FLTMAX;
                if (m.y) v1 = FLTMAX;
                if (v0 < best) { best = v0; bidx = jBase + lcol; }
                if (v1 < best || (v1 == best && jBase + lcol + 1 < bidx)) { best = v1; bidx = jBase + lcol + 1; }
            }
            // reduce across tig quad (lanes g*4 + tig)
#pragma unroll
            for (int o = 1; o < 4; o <<= 1) {
                float v = __shfl_down_sync(0xffffffffu, best, o);
                int   i = __shfl_down_sync(0xffffffffu, bidx, o);
                if (v < best || (v == best && i < bidx)) { best = v; bidx = i; }
            }
            if (tig == 0) { redV[lrow * 4 + wn] = best; redI[lrow * 4 + wn] = bidx; }
        }
    __syncthreads();

    if (tid < 128) {
        float best = redV[tid * 4];
        int bidx = redI[tid * 4];
#pragma unroll
        for (int w = 1; w < 4; w++) {
            float v = redV[tid * 4 + w];
            int   i = redI[tid * 4 + w];
            if (v < best || (v == best && i < bidx)) { best = v; bidx = i; }
        }
        g_blockBest[(size_t)blockIdx.x * NN + mBase + tid] = best;
        g_blockIdx [(size_t)blockIdx.x * NN + mBase + tid] = bidx;
    }
}

__global__ __launch_bounds__(256) void argmin_combine() {
    int row = blockIdx.x * 256 + threadIdx.x;
    float best = g_blockBest[row];
    int bi = g_blockIdx[row];
#pragma unroll 8
    for (int nb = 1; nb < 64; nb++) {
        float v = g_blockBest[(size_t)nb * NN + row];
        int   i = g_blockIdx [(size_t)nb * NN + row];
        if (v < best || (v == best && i < bi)) { best = v; bi = i; }
    }
    g_negIdx[row] = bi;
}

// ---------------------------------------------------------------------------
// per-anchor triplet term (warp per anchor); reference adds EPS per component
// ---------------------------------------------------------------------------
__global__ __launch_bounds__(128) void loss_kernel(const float* __restrict__ X) {
    int a = blockIdx.x * 4 + (threadIdx.x >> 5);
    int lane = threadIdx.x & 31;
    float4 cv = reinterpret_cast<const float4*>(g_centers + (size_t)a * DD)[lane];
    float4 xv = reinterpret_cast<const float4*>(X + (size_t)a * DD)[lane];
    float4 nv = reinterpret_cast<const float4*>(X + (size_t)g_negIdx[a] * DD)[lane];
    const float EPS = 1e-6f;
    float t, sap = 0.f, san = 0.f;
    t = cv.x - xv.x + EPS; sap += t * t;
    t = cv.y - xv.y + EPS; sap += t * t;
    t = cv.z - xv.z + EPS; sap += t * t;
    t = cv.w - xv.w + EPS; sap += t * t;
    t = cv.x - nv.x + EPS; san += t * t;
    t = cv.y - nv.y + EPS; san += t * t;
    t = cv.z - nv.z + EPS; san += t * t;
    t = cv.w - nv.w + EPS; san += t * t;
#pragma unroll
    for (int o = 16; o; o >>= 1) {
        sap += __shfl_xor_sync(0xffffffffu, sap, o);
        san += __shfl_xor_sync(0xffffffffu, san, o);
    }
    if (lane == 0)
        g_loss[a] = fmaxf(sqrtf(sap) - sqrtf(san) + 0.3f, 0.f);
}

__global__ __launch_bounds__(1024) void reduce_kernel(float* out) {
    __shared__ float smr[1024];
    float s = 0.f;
    for (int i = threadIdx.x; i < NN; i += 1024) s += g_loss[i];
    smr[threadIdx.x] = s;
    __syncthreads();
    for (int o = 512; o; o >>= 1) {
        if (threadIdx.x < o) smr[threadIdx.x] += smr[threadIdx.x + o];
        __syncthreads();
    }
    if (threadIdx.x == 0) out[0] = smr[0] * (1.0f / NN);
}

// ---------------------------------------------------------------------------
extern "C" void kernel_launch(void* const* d_in, const int* in_sizes, int n_in,
                              void* d_out, int out_size) {
    const float* X;
    const int* S;
    if (in_sizes[0] == NN * DD) {
        X = (const float*)d_in[0];
        S = (const int*)d_in[1];
    } else {
        X = (const float*)d_in[1];
        S = (const int*)d_in[0];
    }

    cudaFuncSetAttribute(centers_mma, cudaFuncAttributeMaxDynamicSharedMemorySize, 69632);
    cudaFuncSetAttribute(argmin_mma, cudaFuncAttributeMaxDynamicSharedMemorySize, 74752);

    prep_kernel<<<dim3(NN / 32, DD / 32), 256>>>(X);
    x2_kernel<<<NN / 8, 256>>>(X);
    centers_mma<<<dim3(64, 2), 256, 69632>>>(S);
    centers_combine<<<NN / 4, 128>>>();
    argmin_mma<<<dim3(64, 64), 256, 74752>>>(S);
    argmin_combine<<<NN / 256, 256>>>();
    loss_kernel<<<NN / 4, 128>>>(X);
    reduce_kernel<<<1, 1024>>>((float*)d_out);
}

// round 4
// speedup vs baseline: 5.8738x; 1.2439x over previous
#include <cuda_runtime.h>
#include <cuda_bf16.h>
#include <math.h>
#include <stdint.h>

#define NN 8192
#define DD 128
#define FLTMAX 3.402823466e38f
#define STRIDE 136   // padded bf16 row stride (272B): conflict-free frag loads
#define NW 256       // bitmask words per row (8192/32)

// ---------------- device-global scratch (no runtime allocation) -------------
__device__ float          g_centers[(size_t)NN * DD];
__device__ __nv_bfloat16  g_centersB[(size_t)NN * DD];
__device__ __nv_bfloat16  g_Xb [(size_t)NN * DD];   // X bf16 row-major [j][d]
__device__ __nv_bfloat16  g_XbT[(size_t)DD * NN];   // X^T bf16 [d][j]
__device__ uint32_t       g_maskBits[(size_t)NN * NW]; // packed mask bits
__device__ float          g_cntF[NN];
__device__ float          g_x2[NN];
__device__ float          g_c2[NN];
__device__ float          g_part[(size_t)4 * NN * DD];
__device__ float          g_blockBest[(size_t)64 * NN];
__device__ int            g_blockIdx [(size_t)64 * NN];
__device__ int            g_negIdx[NN];
__device__ float          g_loss[NN];

// ---------------- HMMA helper ------------------------------------------------
__device__ __forceinline__ void mma16816(float c[4],
                                         uint32_t a0, uint32_t a1, uint32_t a2, uint32_t a3,
                                         uint32_t b0, uint32_t b1) {
    asm volatile(
        "mma.sync.aligned.m16n8k16.row.col.f32.bf16.bf16.f32 "
        "{%0,%1,%2,%3}, {%4,%5,%6,%7}, {%8,%9}, {%0,%1,%2,%3};"
        : "+f"(c[0]), "+f"(c[1]), "+f"(c[2]), "+f"(c[3])
        : "r"(a0), "r"(a1), "r"(a2), "r"(a3), "r"(b0), "r"(b1));
}

__device__ __forceinline__ uint32_t lds32(const __nv_bfloat16* p) {
    return *reinterpret_cast<const uint32_t*>(p);
}

// two mask bits (i, i+1) -> packed bf16x2 {0|1, 0|1}
__device__ __forceinline__ uint32_t pack2(uint32_t m, int i) {
    return ((m >> i) & 1u) * 0x3F80u + ((m >> (i + 1)) & 1u) * 0x3F800000u;
}

// ---------------------------------------------------------------------------
// pack: similarity int32 -> bitmask + per-row count. warp per row.
// ---------------------------------------------------------------------------
__global__ __launch_bounds__(256) void pack_kernel(const int* __restrict__ S) {
    int row = blockIdx.x * 8 + (threadIdx.x >> 5);
    int lane = threadIdx.x & 31;
    const int* src = S + (size_t)row * NN;
    uint32_t* dst = g_maskBits + (size_t)row * NW;
    int cnt = 0;
#pragma unroll 4
    for (int it = 0; it < 64; it++) {
        int base = it * 128;
        uint32_t b0 = __ballot_sync(0xffffffffu, src[base + lane] != 0);
        uint32_t b1 = __ballot_sync(0xffffffffu, src[base + 32 + lane] != 0);
        uint32_t b2 = __ballot_sync(0xffffffffu, src[base + 64 + lane] != 0);
        uint32_t b3 = __ballot_sync(0xffffffffu, src[base + 96 + lane] != 0);
        if (lane == 0) {
            *reinterpret_cast<uint4*>(dst + it * 4) = make_uint4(b0, b1, b2, b3);
            cnt += __popc(b0) + __popc(b1) + __popc(b2) + __popc(b3);
        }
    }
    if (lane == 0) g_cntF[row] = (float)cnt;
}

// ---------------------------------------------------------------------------
// prep: Xb (bf16), XbT (bf16 transposed) via smem tile transpose
// ---------------------------------------------------------------------------
__global__ __launch_bounds__(256) void prep_kernel(const float* __restrict__ X) {
    __shared__ float tile[32][33];
    int tx = threadIdx.x & 31, ty = threadIdx.x >> 5;
    int j0 = blockIdx.x * 32, d0 = blockIdx.y * 32;
#pragma unroll
    for (int jr = ty; jr < 32; jr += 8) {
        float v = X[(size_t)(j0 + jr) * DD + d0 + tx];
        tile[jr][tx] = v;
        g_Xb[(size_t)(j0 + jr) * DD + d0 + tx] = __float2bfloat16_rn(v);
    }
    __syncthreads();
#pragma unroll
    for (int dr = ty; dr < 32; dr += 8)
        g_XbT[(size_t)(d0 + dr) * NN + j0 + tx] = __float2bfloat16_rn(tile[tx][dr]);
}

__global__ __launch_bounds__(256) void x2_kernel(const float* __restrict__ X) {
    int warp = blockIdx.x * 8 + (threadIdx.x >> 5);
    int lane = threadIdx.x & 31;
    float4 a = reinterpret_cast<const float4*>(X + (size_t)warp * DD)[lane];
    float s = a.x * a.x + a.y * a.y + a.z * a.z + a.w * a.w;
#pragma unroll
    for (int o = 16; o; o >>= 1) s += __shfl_xor_sync(0xffffffffu, s, o);
    if (lane == 0) g_x2[warp] = s;
}

// ---------------------------------------------------------------------------
// centers HMMA: part[128 rows, 128 dims] = mask_bf16 @ XbT over K-split 2048
// grid (64 mb, 4 split), 256 threads (8 warps as 2x4). A from bitmask, B=XbT.
// Register-prefetch pipeline over 16 iterations.
// smem: As[128][136] bf16 + Bs[128][136] bf16 = 69632 B
// ---------------------------------------------------------------------------
__global__ __launch_bounds__(256) void centers_mma() {
    extern __shared__ __align__(16) char sm[];
    __nv_bfloat16* As = reinterpret_cast<__nv_bfloat16*>(sm);
    __nv_bfloat16* Bs = reinterpret_cast<__nv_bfloat16*>(sm + 34816);

    const int tid = threadIdx.x;
    const int wid = tid >> 5, lane = tid & 31;
    const int wm = wid >> 2, wn = wid & 3;          // 2 x 4 warps
    const int g = lane >> 2, tig = lane & 3;
    const int rowBase = blockIdx.x * 128;
    const int split = blockIdx.y;
    const int kBase = split * 2048;

    const int lr = tid >> 1;          // row 0..127
    const int half = tid & 1;         // 64-elem half

    float acc[4][4][4];
#pragma unroll
    for (int mt = 0; mt < 4; mt++)
#pragma unroll
        for (int nt = 0; nt < 4; nt++)
#pragma unroll
            for (int q = 0; q < 4; q++) acc[mt][nt][q] = 0.f;

    // prefetch registers
    uint4 bReg[8];
    uint32_t m0, m1;
    {
        const int k0 = kBase;
        const uint4* bsrc = reinterpret_cast<const uint4*>(g_XbT + (size_t)lr * NN + k0 + half * 64);
#pragma unroll
        for (int u = 0; u < 8; u++) bReg[u] = bsrc[u];
        const uint32_t* mw = g_maskBits + (size_t)(rowBase + lr) * NW + (k0 >> 5) + half * 2;
        m0 = mw[0]; m1 = mw[1];
    }

    for (int it = 0; it < 16; it++) {
        __syncthreads();
        // store prefetched tile
        {
            uint4* bd = reinterpret_cast<uint4*>(Bs + lr * STRIDE + half * 64);
#pragma unroll
            for (int u = 0; u < 8; u++) bd[u] = bReg[u];
            __nv_bfloat16* arow = As + lr * STRIDE + half * 64;
#pragma unroll
            for (int u = 0; u < 4; u++)
                *reinterpret_cast<uint4*>(arow + u * 8) =
                    make_uint4(pack2(m0, u * 8), pack2(m0, u * 8 + 2),
                               pack2(m0, u * 8 + 4), pack2(m0, u * 8 + 6));
#pragma unroll
            for (int u = 0; u < 4; u++)
                *reinterpret_cast<uint4*>(arow + 32 + u * 8) =
                    make_uint4(pack2(m1, u * 8), pack2(m1, u * 8 + 2),
                               pack2(m1, u * 8 + 4), pack2(m1, u * 8 + 6));
        }
        __syncthreads();
        // issue next-iteration loads (overlap with MMA)
        if (it + 1 < 16) {
            const int k0 = kBase + (it + 1) * 128;
            const uint4* bsrc = reinterpret_cast<const uint4*>(g_XbT + (size_t)lr * NN + k0 + half * 64);
#pragma unroll
            for (int u = 0; u < 8; u++) bReg[u] = bsrc[u];
            const uint32_t* mw = g_maskBits + (size_t)(rowBase + lr) * NW + (k0 >> 5) + half * 2;
            m0 = mw[0]; m1 = mw[1];
        }

#pragma unroll
        for (int ks = 0; ks < 8; ks++) {
            const int kk = ks * 16;
            uint32_t a[4][4], b[4][2];
#pragma unroll
            for (int mt = 0; mt < 4; mt++) {
                const __nv_bfloat16* p = As + (wm * 64 + mt * 16 + g) * STRIDE + kk + tig * 2;
                a[mt][0] = lds32(p);
                a[mt][1] = lds32(p + 8 * STRIDE);
                a[mt][2] = lds32(p + 8);
                a[mt][3] = lds32(p + 8 * STRIDE + 8);
            }
#pragma unroll
            for (int nt = 0; nt < 4; nt++) {
                const __nv_bfloat16* p = Bs + (wn * 32 + nt * 8 + g) * STRIDE + kk + tig * 2;
                b[nt][0] = lds32(p);
                b[nt][1] = lds32(p + 8);
            }
#pragma unroll
            for (int mt = 0; mt < 4; mt++)
#pragma unroll
                for (int nt = 0; nt < 4; nt++)
                    mma16816(acc[mt][nt], a[mt][0], a[mt][1], a[mt][2], a[mt][3],
                             b[nt][0], b[nt][1]);
        }
    }

    // epilogue: raw partial sums
#pragma unroll
    for (int mt = 0; mt < 4; mt++)
#pragma unroll
        for (int h = 0; h < 2; h++) {
            int grow = rowBase + wm * 64 + mt * 16 + h * 8 + g;
#pragma unroll
            for (int nt = 0; nt < 4; nt++) {
                int col = wn * 32 + nt * 8 + tig * 2;
                float2 v = make_float2(acc[mt][nt][h * 2], acc[mt][nt][h * 2 + 1]);
                *reinterpret_cast<float2*>(g_part + ((size_t)split * NN + grow) * DD + col) = v;
            }
        }
}

// ---------------------------------------------------------------------------
// centers combine: sum 4 split partials, /count, write fp32 + bf16 + c2
// ---------------------------------------------------------------------------
__global__ __launch_bounds__(128) void centers_combine() {
    int row = blockIdx.x * 4 + (threadIdx.x >> 5);
    int lane = threadIdx.x & 31;
    float inv = 1.0f / g_cntF[row];
    float4 s = make_float4(0.f, 0.f, 0.f, 0.f);
#pragma unroll
    for (int sp = 0; sp < 4; sp++) {
        float4 p = reinterpret_cast<const float4*>(g_part + ((size_t)sp * NN + row) * DD)[lane];
        s.x += p.x; s.y += p.y; s.z += p.z; s.w += p.w;
    }
    s.x *= inv; s.y *= inv; s.z *= inv; s.w *= inv;
    reinterpret_cast<float4*>(g_centers + (size_t)row * DD)[lane] = s;
    __nv_bfloat162 lo = __floats2bfloat162_rn(s.x, s.y);
    __nv_bfloat162 hi = __floats2bfloat162_rn(s.z, s.w);
    uint2 packed = make_uint2(*reinterpret_cast<uint32_t*>(&lo), *reinterpret_cast<uint32_t*>(&hi));
    reinterpret_cast<uint2*>(g_centersB + (size_t)row * DD)[lane] = packed;
    float c2 = s.x * s.x + s.y * s.y + s.z * s.z + s.w * s.w;
#pragma unroll
    for (int o = 16; o; o >>= 1) c2 += __shfl_xor_sync(0xffffffffu, c2, o);
    if (lane == 0) g_c2[row] = c2;
}

// ---------------------------------------------------------------------------
// argmin HMMA: dot[128 rows, 128 j] = centersB @ Xb^T (K=128), fused argmin
// grid (64 nb, 64 mb), 256 threads (8 warps as 2x4). Mask from bitmask.
// ---------------------------------------------------------------------------
__global__ __launch_bounds__(256) void argmin_mma() {
    extern __shared__ __align__(16) char sm[];
    __nv_bfloat16* As = reinterpret_cast<__nv_bfloat16*>(sm);
    __nv_bfloat16* Bs = reinterpret_cast<__nv_bfloat16*>(sm + 34816);
    float* x2s = reinterpret_cast<float*>(sm + 69632);
    float* c2s = x2s + 128;
    float* redV = c2s + 128;
    int*   redI = reinterpret_cast<int*>(redV + 512);

    const int tid = threadIdx.x;
    const int wid = tid >> 5, lane = tid & 31;
    const int wm = wid >> 2, wn = wid & 3;
    const int g = lane >> 2, tig = lane & 3;
    const int mBase = blockIdx.y * 128, jBase = blockIdx.x * 128;

    {
        int lr = tid >> 1, half = tid & 1;
        const uint4* a = reinterpret_cast<const uint4*>(g_centersB + (size_t)(mBase + lr) * DD + half * 64);
        uint4* ad = reinterpret_cast<uint4*>(As + lr * STRIDE + half * 64);
        const uint4* b = reinterpret_cast<const uint4*>(g_Xb + (size_t)(jBase + lr) * DD + half * 64);
        uint4* bd = reinterpret_cast<uint4*>(Bs + lr * STRIDE + half * 64);
#pragma unroll
        for (int u = 0; u < 8; u++) { ad[u] = a[u]; bd[u] = b[u]; }
        if (tid < 32) reinterpret_cast<float4*>(x2s)[tid] = reinterpret_cast<const float4*>(g_x2 + jBase)[tid];
        else if (tid < 64) reinterpret_cast<float4*>(c2s)[tid - 32] = reinterpret_cast<const float4*>(g_c2 + mBase)[tid - 32];
    }
    __syncthreads();

    float acc[4][4][4];
#pragma unroll
    for (int mt = 0; mt < 4; mt++)
#pragma unroll
        for (int nt = 0; nt < 4; nt++)
#pragma unroll
            for (int q = 0; q < 4; q++) acc[mt][nt][q] = 0.f;

#pragma unroll
    for (int ks = 0; ks < 8; ks++) {
        const int kk = ks * 16;
        uint32_t a[4][4], b[4][2];
#pragma unroll
        for (int mt = 0; mt < 4; mt++) {
            const __nv_bfloat16* p = As + (wm * 64 + mt * 16 + g) * STRIDE + kk + tig * 2;
            a[mt][0] = lds32(p);
            a[mt][1] = lds32(p + 8 * STRIDE);
            a[mt][2] = lds32(p + 8);
            a[mt][3] = lds32(p + 8 * STRIDE + 8);
        }
#pragma unroll
        for (int nt = 0; nt < 4; nt++) {
            const __nv_bfloat16* p = Bs + (wn * 32 + nt * 8 + g) * STRIDE + kk + tig * 2;
            b[nt][0] = lds32(p);
            b[nt][1] = lds32(p + 8);
        }
#pragma unroll
        for (int mt = 0; mt < 4; mt++)
#pragma unroll
            for (int nt = 0; nt < 4; nt++)
                mma16816(acc[mt][nt], a[mt][0], a[mt][1], a[mt][2], a[mt][3],
                         b[nt][0], b[nt][1]);
    }

    // fused argmin epilogue: metric max(x2 - 2*dot, -c2), positives -> +inf
    const int wordBase = (jBase >> 5) + wn;   // word wn covers cols wn*32..+31
#pragma unroll
    for (int mt = 0; mt < 4; mt++)
#pragma unroll
        for (int h = 0; h < 2; h++) {
            int lrow = wm * 64 + mt * 16 + h * 8 + g;
            int grow = mBase + lrow;
            float negc2 = -c2s[lrow];
            uint32_t mw = g_maskBits[(size_t)grow * NW + wordBase];
            float best = FLTMAX;
            int bidx = 0x7FFFFFFF;
#pragma unroll
            for (int nt = 0; nt < 4; nt++) {
                int bpos = nt * 8 + tig * 2;
                int lcol = wn * 32 + bpos;
                float v0 = fmaxf(fmaf(-2.f, acc[mt][nt][h * 2 + 0], x2s[lcol + 0]), negc2);
                float v1 = fmaxf(fmaf(-2.f, acc[mt][nt][h * 2 + 1], x2s[lcol + 1]), negc2);
                if ((mw >> bpos) & 1u) v0 = FLTMAX;
                if ((mw >> (bpos + 1)) & 1u) v1 = FLTMAX;
                if (v0 < best) { best = v0; bidx = jBase + lcol; }
                if (v1 < best || (v1 == best && jBase + lcol + 1 < bidx)) { best = v1; bidx = jBase + lcol + 1; }
            }
#pragma unroll
            for (int o = 1; o < 4; o <<= 1) {
                float v = __shfl_down_sync(0xffffffffu, best, o);
                int   i = __shfl_down_sync(0xffffffffu, bidx, o);
                if (v < best || (v == best && i < bidx)) { best = v; bidx = i; }
            }
            if (tig == 0) { redV[lrow * 4 + wn] = best; redI[lrow * 4 + wn] = bidx; }
        }
    __syncthreads();

    if (tid < 128) {
        float best = redV[tid * 4];
        int bidx = redI[tid * 4];
#pragma unroll
        for (int w = 1; w < 4; w++) {
            float v = redV[tid * 4 + w];
            int   i = redI[tid * 4 + w];
            if (v < best || (v == best && i < bidx)) { best = v; bidx = i; }
        }
        g_blockBest[(size_t)blockIdx.x * NN + mBase + tid] = best;
        g_blockIdx [(size_t)blockIdx.x * NN + mBase + tid] = bidx;
    }
}

__global__ __launch_bounds__(256) void argmin_combine() {
    int row = blockIdx.x * 256 + threadIdx.x;
    float best = g_blockBest[row];
    int bi = g_blockIdx[row];
#pragma unroll 8
    for (int nb = 1; nb < 64; nb++) {
        float v = g_blockBest[(size_t)nb * NN + row];
        int   i = g_blockIdx [(size_t)nb * NN + row];
        if (v < best || (v == best && i < bi)) { best = v; bi = i; }
    }
    g_negIdx[row] = bi;
}

// ---------------------------------------------------------------------------
// per-anchor triplet term (warp per anchor); reference adds EPS per component
// ---------------------------------------------------------------------------
__global__ __launch_bounds__(128) void loss_kernel(const float* __restrict__ X) {
    int a = blockIdx.x * 4 + (threadIdx.x >> 5);
    int lane = threadIdx.x & 31;
    float4 cv = reinterpret_cast<const float4*>(g_centers + (size_t)a * DD)[lane];
    float4 xv = reinterpret_cast<const float4*>(X + (size_t)a * DD)[lane];
    float4 nv = reinterpret_cast<const float4*>(X + (size_t)g_negIdx[a] * DD)[lane];
    const float EPS = 1e-6f;
    float t, sap = 0.f, san = 0.f;
    t = cv.x - xv.x + EPS; sap += t * t;
    t = cv.y - xv.y + EPS; sap += t * t;
    t = cv.z - xv.z + EPS; sap += t * t;
    t = cv.w - xv.w + EPS; sap += t * t;
    t = cv.x - nv.x + EPS; san += t * t;
    t = cv.y - nv.y + EPS; san += t * t;
    t = cv.z - nv.z + EPS; san += t * t;
    t = cv.w - nv.w + EPS; san += t * t;
#pragma unroll
    for (int o = 16; o; o >>= 1) {
        sap += __shfl_xor_sync(0xffffffffu, sap, o);
        san += __shfl_xor_sync(0xffffffffu, san, o);
    }
    if (lane == 0)
        g_loss[a] = fmaxf(sqrtf(sap) - sqrtf(san) + 0.3f, 0.f);
}

__global__ __launch_bounds__(1024) void reduce_kernel(float* out) {
    __shared__ float smr[1024];
    float s = 0.f;
    for (int i = threadIdx.x; i < NN; i += 1024) s += g_loss[i];
    smr[threadIdx.x] = s;
    __syncthreads();
    for (int o = 512; o; o >>= 1) {
        if (threadIdx.x < o) smr[threadIdx.x] += smr[threadIdx.x + o];
        __syncthreads();
    }
    if (threadIdx.x == 0) out[0] = smr[0] * (1.0f / NN);
}

// ---------------------------------------------------------------------------
extern "C" void kernel_launch(void* const* d_in, const int* in_sizes, int n_in,
                              void* d_out, int out_size) {
    const float* X;
    const int* S;
    if (in_sizes[0] == NN * DD) {
        X = (const float*)d_in[0];
        S = (const int*)d_in[1];
    } else {
        X = (const float*)d_in[1];
        S = (const int*)d_in[0];
    }

    cudaFuncSetAttribute(centers_mma, cudaFuncAttributeMaxDynamicSharedMemorySize, 69632);
    cudaFuncSetAttribute(argmin_mma, cudaFuncAttributeMaxDynamicSharedMemorySize, 74752);

    pack_kernel<<<NN / 8, 256>>>(S);
    prep_kernel<<<dim3(NN / 32, DD / 32), 256>>>(X);
    x2_kernel<<<NN / 8, 256>>>(X);
    centers_mma<<<dim3(64, 4), 256, 69632>>>();
    centers_combine<<<NN / 4, 128>>>();
    argmin_mma<<<dim3(64, 64), 256, 74752>>>();
    argmin_combine<<<NN / 256, 256>>>();
    loss_kernel<<<NN / 4, 128>>>(X);
    reduce_kernel<<<1, 1024>>>((float*)d_out);
}

// round 5
// speedup vs baseline: 6.1226x; 1.0424x over previous
#include <cuda_runtime.h>
#include <cuda_bf16.h>
#include <math.h>
#include <stdint.h>

#define NN 8192
#define DD 128
#define FLTMAX 3.402823466e38f
#define STRIDE 136   // padded bf16 row stride (272B): conflict-free LDSM rows
#define NW 256       // bitmask words per row (8192/32)

// ---------------- device-global scratch (no runtime allocation) -------------
__device__ float          g_centers[(size_t)NN * DD];
__device__ __nv_bfloat16  g_centersB[(size_t)NN * DD];
__device__ __nv_bfloat16  g_Xb [(size_t)NN * DD];   // X bf16 row-major [j][d]
__device__ __nv_bfloat16  g_XbT[(size_t)DD * NN];   // X^T bf16 [d][j]
__device__ uint32_t       g_maskBits[(size_t)NN * NW]; // packed mask bits
__device__ float          g_cntF[NN];
__device__ float          g_x2[NN];
__device__ float          g_c2[NN];
__device__ float          g_part[(size_t)4 * NN * DD];
__device__ float          g_blockBest[(size_t)64 * NN];
__device__ int            g_blockIdx [(size_t)64 * NN];
__device__ int            g_negIdx[NN];
__device__ float          g_loss[NN];

// ---------------- MMA / LDSM helpers ----------------------------------------
__device__ __forceinline__ void mma16816(float c[4],
                                         uint32_t a0, uint32_t a1, uint32_t a2, uint32_t a3,
                                         uint32_t b0, uint32_t b1) {
    asm volatile(
        "mma.sync.aligned.m16n8k16.row.col.f32.bf16.bf16.f32 "
        "{%0,%1,%2,%3}, {%4,%5,%6,%7}, {%8,%9}, {%0,%1,%2,%3};"
        : "+f"(c[0]), "+f"(c[1]), "+f"(c[2]), "+f"(c[3])
        : "r"(a0), "r"(a1), "r"(a2), "r"(a3), "r"(b0), "r"(b1));
}

__device__ __forceinline__ void ldsm4(uint32_t r[4], uint32_t addr) {
    asm volatile("ldmatrix.sync.aligned.m8n8.x4.shared.b16 {%0,%1,%2,%3}, [%4];"
        : "=r"(r[0]), "=r"(r[1]), "=r"(r[2]), "=r"(r[3]) : "r"(addr));
}

__device__ __forceinline__ uint32_t smem_u32(const void* p) {
    uint32_t a;
    asm("{ .reg .u64 t; cvta.to.shared.u64 t, %1; cvt.u32.u64 %0, t; }" : "=r"(a) : "l"(p));
    return a;
}

// two mask bits (i, i+1) -> packed bf16x2 {0|1, 0|1}
__device__ __forceinline__ uint32_t pack2(uint32_t m, int i) {
    return ((m >> i) & 1u) * 0x3F80u + ((m >> (i + 1)) & 1u) * 0x3F800000u;
}

// ---------------------------------------------------------------------------
// pack: similarity int32 -> bitmask + per-row count. warp per row.
// ---------------------------------------------------------------------------
__global__ __launch_bounds__(256) void pack_kernel(const int* __restrict__ S) {
    int row = blockIdx.x * 8 + (threadIdx.x >> 5);
    int lane = threadIdx.x & 31;
    const int* src = S + (size_t)row * NN;
    uint32_t* dst = g_maskBits + (size_t)row * NW;
    int cnt = 0;
#pragma unroll 4
    for (int it = 0; it < 64; it++) {
        int base = it * 128;
        uint32_t b0 = __ballot_sync(0xffffffffu, src[base + lane] != 0);
        uint32_t b1 = __ballot_sync(0xffffffffu, src[base + 32 + lane] != 0);
        uint32_t b2 = __ballot_sync(0xffffffffu, src[base + 64 + lane] != 0);
        uint32_t b3 = __ballot_sync(0xffffffffu, src[base + 96 + lane] != 0);
        if (lane == 0) {
            *reinterpret_cast<uint4*>(dst + it * 4) = make_uint4(b0, b1, b2, b3);
            cnt += __popc(b0) + __popc(b1) + __popc(b2) + __popc(b3);
        }
    }
    if (lane == 0) g_cntF[row] = (float)cnt;
}

// ---------------------------------------------------------------------------
// prep: Xb (bf16), XbT (bf16 transposed) via smem tile transpose
// ---------------------------------------------------------------------------
__global__ __launch_bounds__(256) void prep_kernel(const float* __restrict__ X) {
    __shared__ float tile[32][33];
    int tx = threadIdx.x & 31, ty = threadIdx.x >> 5;
    int j0 = blockIdx.x * 32, d0 = blockIdx.y * 32;
#pragma unroll
    for (int jr = ty; jr < 32; jr += 8) {
        float v = X[(size_t)(j0 + jr) * DD + d0 + tx];
        tile[jr][tx] = v;
        g_Xb[(size_t)(j0 + jr) * DD + d0 + tx] = __float2bfloat16_rn(v);
    }
    __syncthreads();
#pragma unroll
    for (int dr = ty; dr < 32; dr += 8)
        g_XbT[(size_t)(d0 + dr) * NN + j0 + tx] = __float2bfloat16_rn(tile[tx][dr]);
}

__global__ __launch_bounds__(256) void x2_kernel(const float* __restrict__ X) {
    int warp = blockIdx.x * 8 + (threadIdx.x >> 5);
    int lane = threadIdx.x & 31;
    float4 a = reinterpret_cast<const float4*>(X + (size_t)warp * DD)[lane];
    float s = a.x * a.x + a.y * a.y + a.z * a.z + a.w * a.w;
#pragma unroll
    for (int o = 16; o; o >>= 1) s += __shfl_xor_sync(0xffffffffu, s, o);
    if (lane == 0) g_x2[warp] = s;
}

// ---------------------------------------------------------------------------
// centers HMMA: part[128 rows, 128 dims] = mask_bf16 @ XbT over K-split 2048
// grid (64 mb, 4 split), 256 threads (8 warps as 2x4). LDSM fragment feeds.
// ---------------------------------------------------------------------------
__global__ __launch_bounds__(256) void centers_mma() {
    extern __shared__ __align__(16) char sm[];
    __nv_bfloat16* As = reinterpret_cast<__nv_bfloat16*>(sm);
    __nv_bfloat16* Bs = reinterpret_cast<__nv_bfloat16*>(sm + 34816);

    const int tid = threadIdx.x;
    const int wid = tid >> 5, lane = tid & 31;
    const int wm = wid >> 2, wn = wid & 3;          // 2 x 4 warps
    const int rowBase = blockIdx.x * 128;
    const int split = blockIdx.y;
    const int kBase = split * 2048;

    const int lr = tid >> 1;          // row 0..127
    const int half = tid & 1;         // 64-elem half

    // LDSM lane addressing
    const int l7 = lane & 7, lid8 = lane >> 3;
    const uint32_t asBase = smem_u32(As), bsBase = smem_u32(Bs);
    uint32_t aoff[4], boff[2];
#pragma unroll
    for (int mt = 0; mt < 4; mt++)
        aoff[mt] = asBase + (uint32_t)((wm * 64 + mt * 16 + (lid8 & 1) * 8 + l7) * STRIDE * 2 + (lid8 >> 1) * 16);
#pragma unroll
    for (int np = 0; np < 2; np++)
        boff[np] = bsBase + (uint32_t)((wn * 32 + np * 16 + (lid8 >> 1) * 8 + l7) * STRIDE * 2 + (lid8 & 1) * 16);

    float acc[4][4][4];
#pragma unroll
    for (int mt = 0; mt < 4; mt++)
#pragma unroll
        for (int nt = 0; nt < 4; nt++)
#pragma unroll
            for (int q = 0; q < 4; q++) acc[mt][nt][q] = 0.f;

    // prefetch registers
    uint4 bReg[8];
    uint32_t m0, m1;
    {
        const int k0 = kBase;
        const uint4* bsrc = reinterpret_cast<const uint4*>(g_XbT + (size_t)lr * NN + k0 + half * 64);
#pragma unroll
        for (int u = 0; u < 8; u++) bReg[u] = bsrc[u];
        const uint32_t* mw = g_maskBits + (size_t)(rowBase + lr) * NW + (k0 >> 5) + half * 2;
        m0 = mw[0]; m1 = mw[1];
    }

    for (int it = 0; it < 16; it++) {
        __syncthreads();
        {
            uint4* bd = reinterpret_cast<uint4*>(Bs + lr * STRIDE + half * 64);
#pragma unroll
            for (int u = 0; u < 8; u++) bd[u] = bReg[u];
            __nv_bfloat16* arow = As + lr * STRIDE + half * 64;
#pragma unroll
            for (int u = 0; u < 4; u++)
                *reinterpret_cast<uint4*>(arow + u * 8) =
                    make_uint4(pack2(m0, u * 8), pack2(m0, u * 8 + 2),
                               pack2(m0, u * 8 + 4), pack2(m0, u * 8 + 6));
#pragma unroll
            for (int u = 0; u < 4; u++)
                *reinterpret_cast<uint4*>(arow + 32 + u * 8) =
                    make_uint4(pack2(m1, u * 8), pack2(m1, u * 8 + 2),
                               pack2(m1, u * 8 + 4), pack2(m1, u * 8 + 6));
        }
        __syncthreads();
        if (it + 1 < 16) {
            const int k0 = kBase + (it + 1) * 128;
            const uint4* bsrc = reinterpret_cast<const uint4*>(g_XbT + (size_t)lr * NN + k0 + half * 64);
#pragma unroll
            for (int u = 0; u < 8; u++) bReg[u] = bsrc[u];
            const uint32_t* mw = g_maskBits + (size_t)(rowBase + lr) * NW + (k0 >> 5) + half * 2;
            m0 = mw[0]; m1 = mw[1];
        }

#pragma unroll
        for (int ks = 0; ks < 8; ks++) {
            const uint32_t kb = ks * 32;  // 16 bf16 = 32 bytes
            uint32_t a[4][4], b[2][4];
#pragma unroll
            for (int mt = 0; mt < 4; mt++) ldsm4(a[mt], aoff[mt] + kb);
#pragma unroll
            for (int np = 0; np < 2; np++) ldsm4(b[np], boff[np] + kb);
#pragma unroll
            for (int mt = 0; mt < 4; mt++)
#pragma unroll
                for (int nt = 0; nt < 4; nt++)
                    mma16816(acc[mt][nt], a[mt][0], a[mt][1], a[mt][2], a[mt][3],
                             b[nt >> 1][(nt & 1) * 2], b[nt >> 1][(nt & 1) * 2 + 1]);
        }
    }

    const int g = lane >> 2, tig = lane & 3;
#pragma unroll
    for (int mt = 0; mt < 4; mt++)
#pragma unroll
        for (int h = 0; h < 2; h++) {
            int grow = rowBase + wm * 64 + mt * 16 + h * 8 + g;
#pragma unroll
            for (int nt = 0; nt < 4; nt++) {
                int col = wn * 32 + nt * 8 + tig * 2;
                float2 v = make_float2(acc[mt][nt][h * 2], acc[mt][nt][h * 2 + 1]);
                *reinterpret_cast<float2*>(g_part + ((size_t)split * NN + grow) * DD + col) = v;
            }
        }
}

// ---------------------------------------------------------------------------
// centers combine: sum 4 split partials, /count, write fp32 + bf16 + c2
// ---------------------------------------------------------------------------
__global__ __launch_bounds__(128) void centers_combine() {
    int row = blockIdx.x * 4 + (threadIdx.x >> 5);
    int lane = threadIdx.x & 31;
    float inv = 1.0f / g_cntF[row];
    float4 s = make_float4(0.f, 0.f, 0.f, 0.f);
#pragma unroll
    for (int sp = 0; sp < 4; sp++) {
        float4 p = reinterpret_cast<const float4*>(g_part + ((size_t)sp * NN + row) * DD)[lane];
        s.x += p.x; s.y += p.y; s.z += p.z; s.w += p.w;
    }
    s.x *= inv; s.y *= inv; s.z *= inv; s.w *= inv;
    reinterpret_cast<float4*>(g_centers + (size_t)row * DD)[lane] = s;
    __nv_bfloat162 lo = __floats2bfloat162_rn(s.x, s.y);
    __nv_bfloat162 hi = __floats2bfloat162_rn(s.z, s.w);
    uint2 packed = make_uint2(*reinterpret_cast<uint32_t*>(&lo), *reinterpret_cast<uint32_t*>(&hi));
    reinterpret_cast<uint2*>(g_centersB + (size_t)row * DD)[lane] = packed;
    float c2 = s.x * s.x + s.y * s.y + s.z * s.z + s.w * s.w;
#pragma unroll
    for (int o = 16; o; o >>= 1) c2 += __shfl_xor_sync(0xffffffffu, c2, o);
    if (lane == 0) g_c2[row] = c2;
}

// ---------------------------------------------------------------------------
// argmin HMMA: dot[128 rows, 128 j] = centersB @ Xb^T (K=128), fused argmin
// grid (64 nb, 64 mb), 256 threads (8 warps as 2x4). LDSM fragment feeds.
// ---------------------------------------------------------------------------
__global__ __launch_bounds__(256) void argmin_mma() {
    extern __shared__ __align__(16) char sm[];
    __nv_bfloat16* As = reinterpret_cast<__nv_bfloat16*>(sm);
    __nv_bfloat16* Bs = reinterpret_cast<__nv_bfloat16*>(sm + 34816);
    float* x2s = reinterpret_cast<float*>(sm + 69632);
    float* c2s = x2s + 128;
    float* redV = c2s + 128;
    int*   redI = reinterpret_cast<int*>(redV + 512);

    const int tid = threadIdx.x;
    const int wid = tid >> 5, lane = tid & 31;
    const int wm = wid >> 2, wn = wid & 3;
    const int g = lane >> 2, tig = lane & 3;
    const int mBase = blockIdx.y * 128, jBase = blockIdx.x * 128;

    {
        int lr = tid >> 1, half = tid & 1;
        const uint4* a = reinterpret_cast<const uint4*>(g_centersB + (size_t)(mBase + lr) * DD + half * 64);
        uint4* ad = reinterpret_cast<uint4*>(As + lr * STRIDE + half * 64);
        const uint4* b = reinterpret_cast<const uint4*>(g_Xb + (size_t)(jBase + lr) * DD + half * 64);
        uint4* bd = reinterpret_cast<uint4*>(Bs + lr * STRIDE + half * 64);
#pragma unroll
        for (int u = 0; u < 8; u++) { ad[u] = a[u]; bd[u] = b[u]; }
        if (tid < 32) reinterpret_cast<float4*>(x2s)[tid] = reinterpret_cast<const float4*>(g_x2 + jBase)[tid];
        else if (tid < 64) reinterpret_cast<float4*>(c2s)[tid - 32] = reinterpret_cast<const float4*>(g_c2 + mBase)[tid - 32];
    }

    const int l7 = lane & 7, lid8 = lane >> 3;
    const uint32_t asBase = smem_u32(As), bsBase = smem_u32(Bs);
    uint32_t aoff[4], boff[2];
#pragma unroll
    for (int mt = 0; mt < 4; mt++)
        aoff[mt] = asBase + (uint32_t)((wm * 64 + mt * 16 + (lid8 & 1) * 8 + l7) * STRIDE * 2 + (lid8 >> 1) * 16);
#pragma unroll
    for (int np = 0; np < 2; np++)
        boff[np] = bsBase + (uint32_t)((wn * 32 + np * 16 + (lid8 >> 1) * 8 + l7) * STRIDE * 2 + (lid8 & 1) * 16);

    __syncthreads();

    float acc[4][4][4];
#pragma unroll
    for (int mt = 0; mt < 4; mt++)
#pragma unroll
        for (int nt = 0; nt < 4; nt++)
#pragma unroll
            for (int q = 0; q < 4; q++) acc[mt][nt][q] = 0.f;

#pragma unroll
    for (int ks = 0; ks < 8; ks++) {
        const uint32_t kb = ks * 32;
        uint32_t a[4][4], b[2][4];
#pragma unroll
        for (int mt = 0; mt < 4; mt++) ldsm4(a[mt], aoff[mt] + kb);
#pragma unroll
        for (int np = 0; np < 2; np++) ldsm4(b[np], boff[np] + kb);
#pragma unroll
        for (int mt = 0; mt < 4; mt++)
#pragma unroll
            for (int nt = 0; nt < 4; nt++)
                mma16816(acc[mt][nt], a[mt][0], a[mt][1], a[mt][2], a[mt][3],
                         b[nt >> 1][(nt & 1) * 2], b[nt >> 1][(nt & 1) * 2 + 1]);
    }

    // fused argmin epilogue: metric max(x2 - 2*dot, -c2), positives -> +inf
    const int wordBase = (jBase >> 5) + wn;
#pragma unroll
    for (int mt = 0; mt < 4; mt++)
#pragma unroll
        for (int h = 0; h < 2; h++) {
            int lrow = wm * 64 + mt * 16 + h * 8 + g;
            int grow = mBase + lrow;
            float negc2 = -c2s[lrow];
            uint32_t mw = g_maskBits[(size_t)grow * NW + wordBase];
            float best = FLTMAX;
            int bidx = 0x7FFFFFFF;
#pragma unroll
            for (int nt = 0; nt < 4; nt++) {
                int bpos = nt * 8 + tig * 2;
                int lcol = wn * 32 + bpos;
                float v0 = fmaxf(fmaf(-2.f, acc[mt][nt][h * 2 + 0], x2s[lcol + 0]), negc2);
                float v1 = fmaxf(fmaf(-2.f, acc[mt][nt][h * 2 + 1], x2s[lcol + 1]), negc2);
                if ((mw >> bpos) & 1u) v0 = FLTMAX;
                if ((mw >> (bpos + 1)) & 1u) v1 = FLTMAX;
                if (v0 < best) { best = v0; bidx = jBase + lcol; }
                if (v1 < best || (v1 == best && jBase + lcol + 1 < bidx)) { best = v1; bidx = jBase + lcol + 1; }
            }
#pragma unroll
            for (int o = 1; o < 4; o <<= 1) {
                float v = __shfl_down_sync(0xffffffffu, best, o);
                int   i = __shfl_down_sync(0xffffffffu, bidx, o);
                if (v < best || (v == best && i < bidx)) { best = v; bidx = i; }
            }
            if (tig == 0) { redV[lrow * 4 + wn] = best; redI[lrow * 4 + wn] = bidx; }
        }
    __syncthreads();

    if (tid < 128) {
        float best = redV[tid * 4];
        int bidx = redI[tid * 4];
#pragma unroll
        for (int w = 1; w < 4; w++) {
            float v = redV[tid * 4 + w];
            int   i = redI[tid * 4 + w];
            if (v < best || (v == best && i < bidx)) { best = v; bidx = i; }
        }
        g_blockBest[(size_t)blockIdx.x * NN + mBase + tid] = best;
        g_blockIdx [(size_t)blockIdx.x * NN + mBase + tid] = bidx;
    }
}

__global__ __launch_bounds__(256) void argmin_combine() {
    int row = blockIdx.x * 256 + threadIdx.x;
    float best = g_blockBest[row];
    int bi = g_blockIdx[row];
#pragma unroll 8
    for (int nb = 1; nb < 64; nb++) {
        float v = g_blockBest[(size_t)nb * NN + row];
        int   i = g_blockIdx [(size_t)nb * NN + row];
        if (v < best || (v == best && i < bi)) { best = v; bi = i; }
    }
    g_negIdx[row] = bi;
}

// ---------------------------------------------------------------------------
// per-anchor triplet term (warp per anchor); reference adds EPS per component
// ---------------------------------------------------------------------------
__global__ __launch_bounds__(128) void loss_kernel(const float* __restrict__ X) {
    int a = blockIdx.x * 4 + (threadIdx.x >> 5);
    int lane = threadIdx.x & 31;
    float4 cv = reinterpret_cast<const float4*>(g_centers + (size_t)a * DD)[lane];
    float4 xv = reinterpret_cast<const float4*>(X + (size_t)a * DD)[lane];
    float4 nv = reinterpret_cast<const float4*>(X + (size_t)g_negIdx[a] * DD)[lane];
    const float EPS = 1e-6f;
    float t, sap = 0.f, san = 0.f;
    t = cv.x - xv.x + EPS; sap += t * t;
    t = cv.y - xv.y + EPS; sap += t * t;
    t = cv.z - xv.z + EPS; sap += t * t;
    t = cv.w - xv.w + EPS; sap += t * t;
    t = cv.x - nv.x + EPS; san += t * t;
    t = cv.y - nv.y + EPS; san += t * t;
    t = cv.z - nv.z + EPS; san += t * t;
    t = cv.w - nv.w + EPS; san += t * t;
#pragma unroll
    for (int o = 16; o; o >>= 1) {
        sap += __shfl_xor_sync(0xffffffffu, sap, o);
        san += __shfl_xor_sync(0xffffffffu, san, o);
    }
    if (lane == 0)
        g_loss[a] = fmaxf(sqrtf(sap) - sqrtf(san) + 0.3f, 0.f);
}

__global__ __launch_bounds__(1024) void reduce_kernel(float* out) {
    __shared__ float smr[1024];
    float s = 0.f;
    for (int i = threadIdx.x; i < NN; i += 1024) s += g_loss[i];
    smr[threadIdx.x] = s;
    __syncthreads();
    for (int o = 512; o; o >>= 1) {
        if (threadIdx.x < o) smr[threadIdx.x] += smr[threadIdx.x + o];
        __syncthreads();
    }
    if (threadIdx.x == 0) out[0] = smr[0] * (1.0f / NN);
}

// ---------------------------------------------------------------------------
extern "C" void kernel_launch(void* const* d_in, const int* in_sizes, int n_in,
                              void* d_out, int out_size) {
    const float* X;
    const int* S;
    if (in_sizes[0] == NN * DD) {
        X = (const float*)d_in[0];
        S = (const int*)d_in[1];
    } else {
        X = (const float*)d_in[1];
        S = (const int*)d_in[0];
    }

    cudaFuncSetAttribute(centers_mma, cudaFuncAttributeMaxDynamicSharedMemorySize, 69632);
    cudaFuncSetAttribute(argmin_mma, cudaFuncAttributeMaxDynamicSharedMemorySize, 74752);

    pack_kernel<<<NN / 8, 256>>>(S);
    prep_kernel<<<dim3(NN / 32, DD / 32), 256>>>(X);
    x2_kernel<<<NN / 8, 256>>>(X);
    centers_mma<<<dim3(64, 4), 256, 69632>>>();
    centers_combine<<<NN / 4, 128>>>();
    argmin_mma<<<dim3(64, 64), 256, 74752>>>();
    argmin_combine<<<NN / 256, 256>>>();
    loss_kernel<<<NN / 4, 128>>>(X);
    reduce_kernel<<<1, 1024>>>((float*)d_out);
}

// round 6
// speedup vs baseline: 7.4062x; 1.2096x over previous
#include <cuda_runtime.h>
#include <cuda_bf16.h>
#include <math.h>
#include <stdint.h>

#define NN 8192
#define DD 128
#define FLTMAX 3.402823466e38f
#define STRIDE 136   // padded bf16 row stride (272B): conflict-free LDSM rows
#define NW 256       // bitmask words per row (8192/32)

// ---------------- device-global scratch (no runtime allocation) -------------
__device__ float          g_centers[(size_t)NN * DD];
__device__ __nv_bfloat16  g_centersB[(size_t)NN * DD];
__device__ __nv_bfloat16  g_Xb [(size_t)NN * DD];   // X bf16 row-major [j][d]
__device__ __nv_bfloat16  g_XbT[(size_t)DD * NN];   // X^T bf16 [d][j]
__device__ uint32_t       g_maskBits[(size_t)NN * NW]; // packed mask bits
__device__ float          g_cntF[NN];
__device__ float          g_x2[NN];
__device__ float          g_c2[NN];
__device__ float          g_part[(size_t)2 * NN * DD];
__device__ float          g_blockBest[(size_t)16 * NN];
__device__ int            g_blockIdx [(size_t)16 * NN];
__device__ int            g_negIdx[NN];
__device__ float          g_loss[NN];

// ---------------- MMA / LDSM / cp.async helpers ------------------------------
__device__ __forceinline__ void mma16816(float c[4],
                                         uint32_t a0, uint32_t a1, uint32_t a2, uint32_t a3,
                                         uint32_t b0, uint32_t b1) {
    asm volatile(
        "mma.sync.aligned.m16n8k16.row.col.f32.bf16.bf16.f32 "
        "{%0,%1,%2,%3}, {%4,%5,%6,%7}, {%8,%9}, {%0,%1,%2,%3};"
        : "+f"(c[0]), "+f"(c[1]), "+f"(c[2]), "+f"(c[3])
        : "r"(a0), "r"(a1), "r"(a2), "r"(a3), "r"(b0), "r"(b1));
}

__device__ __forceinline__ void ldsm4(uint32_t r[4], uint32_t addr) {
    asm volatile("ldmatrix.sync.aligned.m8n8.x4.shared.b16 {%0,%1,%2,%3}, [%4];"
        : "=r"(r[0]), "=r"(r[1]), "=r"(r[2]), "=r"(r[3]) : "r"(addr));
}

__device__ __forceinline__ uint32_t smem_u32(const void* p) {
    uint32_t a;
    asm("{ .reg .u64 t; cvta.to.shared.u64 t, %1; cvt.u32.u64 %0, t; }" : "=r"(a) : "l"(p));
    return a;
}

#define CP_ASYNC16(dst, src) \
    asm volatile("cp.async.cg.shared.global [%0], [%1], 16;" :: "r"(dst), "l"(src))
#define CP_COMMIT() asm volatile("cp.async.commit_group;" ::: "memory")
#define CP_WAIT0()  asm volatile("cp.async.wait_group 0;" ::: "memory")

// two mask bits (i, i+1) -> packed bf16x2 {0|1, 0|1}
__device__ __forceinline__ uint32_t pack2(uint32_t m, int i) {
    return ((m >> i) & 1u) * 0x3F80u + ((m >> (i + 1)) & 1u) * 0x3F800000u;
}

// ---------------------------------------------------------------------------
// pack: similarity int32 -> bitmask + per-row count. warp per row.
// ---------------------------------------------------------------------------
__global__ __launch_bounds__(256) void pack_kernel(const int* __restrict__ S) {
    int row = blockIdx.x * 8 + (threadIdx.x >> 5);
    int lane = threadIdx.x & 31;
    const int* src = S + (size_t)row * NN;
    uint32_t* dst = g_maskBits + (size_t)row * NW;
    int cnt = 0;
#pragma unroll 4
    for (int it = 0; it < 64; it++) {
        int base = it * 128;
        uint32_t b0 = __ballot_sync(0xffffffffu, src[base + lane] != 0);
        uint32_t b1 = __ballot_sync(0xffffffffu, src[base + 32 + lane] != 0);
        uint32_t b2 = __ballot_sync(0xffffffffu, src[base + 64 + lane] != 0);
        uint32_t b3 = __ballot_sync(0xffffffffu, src[base + 96 + lane] != 0);
        if (lane == 0) {
            *reinterpret_cast<uint4*>(dst + it * 4) = make_uint4(b0, b1, b2, b3);
            cnt += __popc(b0) + __popc(b1) + __popc(b2) + __popc(b3);
        }
    }
    if (lane == 0) g_cntF[row] = (float)cnt;
}

// ---------------------------------------------------------------------------
// prep: Xb (bf16), XbT (bf16 transposed) via smem tile transpose
// ---------------------------------------------------------------------------
__global__ __launch_bounds__(256) void prep_kernel(const float* __restrict__ X) {
    __shared__ float tile[32][33];
    int tx = threadIdx.x & 31, ty = threadIdx.x >> 5;
    int j0 = blockIdx.x * 32, d0 = blockIdx.y * 32;
#pragma unroll
    for (int jr = ty; jr < 32; jr += 8) {
        float v = X[(size_t)(j0 + jr) * DD + d0 + tx];
        tile[jr][tx] = v;
        g_Xb[(size_t)(j0 + jr) * DD + d0 + tx] = __float2bfloat16_rn(v);
    }
    __syncthreads();
#pragma unroll
    for (int dr = ty; dr < 32; dr += 8)
        g_XbT[(size_t)(d0 + dr) * NN + j0 + tx] = __float2bfloat16_rn(tile[tx][dr]);
}

__global__ __launch_bounds__(256) void x2_kernel(const float* __restrict__ X) {
    int warp = blockIdx.x * 8 + (threadIdx.x >> 5);
    int lane = threadIdx.x & 31;
    float4 a = reinterpret_cast<const float4*>(X + (size_t)warp * DD)[lane];
    float s = a.x * a.x + a.y * a.y + a.z * a.z + a.w * a.w;
#pragma unroll
    for (int o = 16; o; o >>= 1) s += __shfl_xor_sync(0xffffffffu, s, o);
    if (lane == 0) g_x2[warp] = s;
}

// ---------------------------------------------------------------------------
// centers HMMA: part[128 rows, 128 dims] = mask_bf16 @ XbT over K-split 4096
// grid (64 mb, 2 split) = 128 CTAs (single wave), 256 threads (8 warps 2x4).
// cp.async double-buffered B + mask words; A expanded in smem per iter.
// smem: A @0 (34816) | B0 @34816 | B1 @69632 | M0 @104448 (2KB) | M1 @106496
// ---------------------------------------------------------------------------
#define CEN_SM_B(buf)  (34816 + (buf) * 34816)
#define CEN_SM_M(buf)  (104448 + (buf) * 2048)
#define CEN_SM_TOTAL   108544

__global__ __launch_bounds__(256) void centers_mma() {
    extern __shared__ __align__(16) char sm[];
    const uint32_t smb = smem_u32(sm);
    __nv_bfloat16* As = reinterpret_cast<__nv_bfloat16*>(sm);

    const int tid = threadIdx.x;
    const int wid = tid >> 5, lane = tid & 31;
    const int wm = wid >> 2, wn = wid & 3;          // 2 x 4 warps
    const int rowBase = blockIdx.x * 128;
    const int split = blockIdx.y;
    const int kBase = split * 4096;

    const int lr = tid >> 1;          // row 0..127
    const int half = tid & 1;         // 64-elem half

    // LDSM lane addressing (A fixed buffer; B per-buffer base)
    const int l7 = lane & 7, lid8 = lane >> 3;
    uint32_t aoff[4], boffRel[2];
#pragma unroll
    for (int mt = 0; mt < 4; mt++)
        aoff[mt] = smb + (uint32_t)((wm * 64 + mt * 16 + (lid8 & 1) * 8 + l7) * STRIDE * 2 + (lid8 >> 1) * 16);
#pragma unroll
    for (int np = 0; np < 2; np++)
        boffRel[np] = (uint32_t)((wn * 32 + np * 16 + (lid8 >> 1) * 8 + l7) * STRIDE * 2 + (lid8 & 1) * 16);

    float acc[4][4][4];
#pragma unroll
    for (int mt = 0; mt < 4; mt++)
#pragma unroll
        for (int nt = 0; nt < 4; nt++)
#pragma unroll
            for (int q = 0; q < 4; q++) acc[mt][nt][q] = 0.f;

    // issue loads for iter 0
    {
        const int k0 = kBase;
        uint32_t bdst = smb + CEN_SM_B(0) + (uint32_t)(lr * STRIDE + half * 64) * 2;
        const __nv_bfloat16* bsrc = g_XbT + (size_t)lr * NN + k0 + half * 64;
#pragma unroll
        for (int u = 0; u < 8; u++) CP_ASYNC16(bdst + u * 16, bsrc + u * 8);
        if (tid < 128) {
            uint32_t mdst = smb + CEN_SM_M(0) + tid * 16;
            CP_ASYNC16(mdst, g_maskBits + (size_t)(rowBase + tid) * NW + (k0 >> 5));
        }
        CP_COMMIT();
    }

    for (int it = 0; it < 32; it++) {
        const int buf = it & 1;
        CP_WAIT0();
        __syncthreads();   // buffers ready; previous compute (A reads) done

        // prefetch it+1 into other buffers
        if (it + 1 < 32) {
            const int k0 = kBase + (it + 1) * 128;
            uint32_t bdst = smb + CEN_SM_B(buf ^ 1) + (uint32_t)(lr * STRIDE + half * 64) * 2;
            const __nv_bfloat16* bsrc = g_XbT + (size_t)lr * NN + k0 + half * 64;
#pragma unroll
            for (int u = 0; u < 8; u++) CP_ASYNC16(bdst + u * 16, bsrc + u * 8);
            if (tid < 128) {
                uint32_t mdst = smb + CEN_SM_M(buf ^ 1) + tid * 16;
                CP_ASYNC16(mdst, g_maskBits + (size_t)(rowBase + tid) * NW + (k0 >> 5));
            }
            CP_COMMIT();
        }

        // expand A tile: mask words (smem) -> bf16 0/1 into As
        {
            const uint32_t* mrow = reinterpret_cast<const uint32_t*>(sm + CEN_SM_M(buf)) + lr * 4 + half * 2;
            uint32_t m0 = mrow[0], m1 = mrow[1];
            __nv_bfloat16* arow = As + lr * STRIDE + half * 64;
#pragma unroll
            for (int u = 0; u < 4; u++)
                *reinterpret_cast<uint4*>(arow + u * 8) =
                    make_uint4(pack2(m0, u * 8), pack2(m0, u * 8 + 2),
                               pack2(m0, u * 8 + 4), pack2(m0, u * 8 + 6));
#pragma unroll
            for (int u = 0; u < 4; u++)
                *reinterpret_cast<uint4*>(arow + 32 + u * 8) =
                    make_uint4(pack2(m1, u * 8), pack2(m1, u * 8 + 2),
                               pack2(m1, u * 8 + 4), pack2(m1, u * 8 + 6));
        }
        __syncthreads();

        const uint32_t bbase = smb + CEN_SM_B(buf);
#pragma unroll
        for (int ks = 0; ks < 8; ks++) {
            const uint32_t kb = ks * 32;  // 16 bf16 = 32 bytes
            uint32_t a[4][4], b[2][4];
#pragma unroll
            for (int mt = 0; mt < 4; mt++) ldsm4(a[mt], aoff[mt] + kb);
#pragma unroll
            for (int np = 0; np < 2; np++) ldsm4(b[np], bbase + boffRel[np] + kb);
#pragma unroll
            for (int mt = 0; mt < 4; mt++)
#pragma unroll
                for (int nt = 0; nt < 4; nt++)
                    mma16816(acc[mt][nt], a[mt][0], a[mt][1], a[mt][2], a[mt][3],
                             b[nt >> 1][(nt & 1) * 2], b[nt >> 1][(nt & 1) * 2 + 1]);
        }
    }

    const int g = lane >> 2, tig = lane & 3;
#pragma unroll
    for (int mt = 0; mt < 4; mt++)
#pragma unroll
        for (int h = 0; h < 2; h++) {
            int grow = rowBase + wm * 64 + mt * 16 + h * 8 + g;
#pragma unroll
            for (int nt = 0; nt < 4; nt++) {
                int col = wn * 32 + nt * 8 + tig * 2;
                float2 v = make_float2(acc[mt][nt][h * 2], acc[mt][nt][h * 2 + 1]);
                *reinterpret_cast<float2*>(g_part + ((size_t)split * NN + grow) * DD + col) = v;
            }
        }
}

// ---------------------------------------------------------------------------
// centers combine: sum 2 split partials, /count, write fp32 + bf16 + c2
// ---------------------------------------------------------------------------
__global__ __launch_bounds__(128) void centers_combine() {
    int row = blockIdx.x * 4 + (threadIdx.x >> 5);
    int lane = threadIdx.x & 31;
    float inv = 1.0f / g_cntF[row];
    float4 p0 = reinterpret_cast<const float4*>(g_part + (size_t)row * DD)[lane];
    float4 p1 = reinterpret_cast<const float4*>(g_part + ((size_t)NN + row) * DD)[lane];
    float4 s = make_float4((p0.x + p1.x) * inv, (p0.y + p1.y) * inv,
                           (p0.z + p1.z) * inv, (p0.w + p1.w) * inv);
    reinterpret_cast<float4*>(g_centers + (size_t)row * DD)[lane] = s;
    __nv_bfloat162 lo = __floats2bfloat162_rn(s.x, s.y);
    __nv_bfloat162 hi = __floats2bfloat162_rn(s.z, s.w);
    uint2 packed = make_uint2(*reinterpret_cast<uint32_t*>(&lo), *reinterpret_cast<uint32_t*>(&hi));
    reinterpret_cast<uint2*>(g_centersB + (size_t)row * DD)[lane] = packed;
    float c2 = s.x * s.x + s.y * s.y + s.z * s.z + s.w * s.w;
#pragma unroll
    for (int o = 16; o; o >>= 1) c2 += __shfl_xor_sync(0xffffffffu, c2, o);
    if (lane == 0) g_c2[row] = c2;
}

// ---------------------------------------------------------------------------
// argmin HMMA: dot[128 rows, 128 j] = centersB @ Xb^T (K=128), fused argmin.
// grid (16 nb, 64 mb) = 1024 CTAs; each CTA loops over 4 j-tiles with
// cp.async double-buffered B. A tile loaded once. Running best in registers.
// smem: A @0 | B0 @34816 | B1 @69632 | x2 @104448 (2KB) | c2 @106496 (512B)
//       redV @107008 (2KB) | redI @109056 (2KB)  total 111104
// ---------------------------------------------------------------------------
#define ARG_SM_B(buf)  (34816 + (buf) * 34816)
#define ARG_SM_X2      104448
#define ARG_SM_C2      106496
#define ARG_SM_RV      107008
#define ARG_SM_RI      109056
#define ARG_SM_TOTAL   111104

__global__ __launch_bounds__(256) void argmin_mma() {
    extern __shared__ __align__(16) char sm[];
    const uint32_t smb = smem_u32(sm);
    float* x2s = reinterpret_cast<float*>(sm + ARG_SM_X2);
    float* c2s = reinterpret_cast<float*>(sm + ARG_SM_C2);
    float* redV = reinterpret_cast<float*>(sm + ARG_SM_RV);
    int*   redI = reinterpret_cast<int*>(sm + ARG_SM_RI);

    const int tid = threadIdx.x;
    const int wid = tid >> 5, lane = tid & 31;
    const int wm = wid >> 2, wn = wid & 3;
    const int g = lane >> 2, tig = lane & 3;
    const int mBase = blockIdx.y * 128;
    const int jBase0 = blockIdx.x * 512;

    const int lr = tid >> 1, half = tid & 1;

    // prologue loads: A tile, x2 (512 floats), c2 (128 floats), B tile jt=0
    {
        uint32_t adst = smb + (uint32_t)(lr * STRIDE + half * 64) * 2;
        const __nv_bfloat16* asrc = g_centersB + (size_t)(mBase + lr) * DD + half * 64;
#pragma unroll
        for (int u = 0; u < 8; u++) CP_ASYNC16(adst + u * 16, asrc + u * 8);
        uint32_t bdst = smb + ARG_SM_B(0) + (uint32_t)(lr * STRIDE + half * 64) * 2;
        const __nv_bfloat16* bsrc = g_Xb + (size_t)(jBase0 + lr) * DD + half * 64;
#pragma unroll
        for (int u = 0; u < 8; u++) CP_ASYNC16(bdst + u * 16, bsrc + u * 8);
        if (tid < 128) CP_ASYNC16(smb + ARG_SM_X2 + tid * 16, g_x2 + jBase0 + tid * 4);
        else if (tid < 160) CP_ASYNC16(smb + ARG_SM_C2 + (tid - 128) * 16, g_c2 + mBase + (tid - 128) * 4);
        CP_COMMIT();
    }

    // LDSM addressing
    const int l7 = lane & 7, lid8 = lane >> 3;
    uint32_t aoff[4], boffRel[2];
#pragma unroll
    for (int mt = 0; mt < 4; mt++)
        aoff[mt] = smb + (uint32_t)((wm * 64 + mt * 16 + (lid8 & 1) * 8 + l7) * STRIDE * 2 + (lid8 >> 1) * 16);
#pragma unroll
    for (int np = 0; np < 2; np++)
        boffRel[np] = (uint32_t)((wn * 32 + np * 16 + (lid8 >> 1) * 8 + l7) * STRIDE * 2 + (lid8 & 1) * 16);

    float best[4][2];
    int   bidx[4][2];
#pragma unroll
    for (int mt = 0; mt < 4; mt++)
#pragma unroll
        for (int h = 0; h < 2; h++) { best[mt][h] = FLTMAX; bidx[mt][h] = 0x7FFFFFFF; }

    for (int jt = 0; jt < 4; jt++) {
        const int buf = jt & 1;
        const int jBase = jBase0 + jt * 128;
        CP_WAIT0();
        __syncthreads();

        if (jt + 1 < 4) {
            uint32_t bdst = smb + ARG_SM_B(buf ^ 1) + (uint32_t)(lr * STRIDE + half * 64) * 2;
            const __nv_bfloat16* bsrc = g_Xb + (size_t)(jBase0 + (jt + 1) * 128 + lr) * DD + half * 64;
#pragma unroll
            for (int u = 0; u < 8; u++) CP_ASYNC16(bdst + u * 16, bsrc + u * 8);
            CP_COMMIT();
        }

        float acc[4][4][4];
#pragma unroll
        for (int mt = 0; mt < 4; mt++)
#pragma unroll
            for (int nt = 0; nt < 4; nt++)
#pragma unroll
                for (int q = 0; q < 4; q++) acc[mt][nt][q] = 0.f;

        const uint32_t bbase = smb + ARG_SM_B(buf);
#pragma unroll
        for (int ks = 0; ks < 8; ks++) {
            const uint32_t kb = ks * 32;
            uint32_t a[4][4], b[2][4];
#pragma unroll
            for (int mt = 0; mt < 4; mt++) ldsm4(a[mt], aoff[mt] + kb);
#pragma unroll
            for (int np = 0; np < 2; np++) ldsm4(b[np], bbase + boffRel[np] + kb);
#pragma unroll
            for (int mt = 0; mt < 4; mt++)
#pragma unroll
                for (int nt = 0; nt < 4; nt++)
                    mma16816(acc[mt][nt], a[mt][0], a[mt][1], a[mt][2], a[mt][3],
                             b[nt >> 1][(nt & 1) * 2], b[nt >> 1][(nt & 1) * 2 + 1]);
        }

        // fused argmin update: metric max(x2 - 2*dot, -c2), positives -> +inf
        const int wordIdx = (jBase >> 5) + wn;
#pragma unroll
        for (int mt = 0; mt < 4; mt++)
#pragma unroll
            for (int h = 0; h < 2; h++) {
                int lrow = wm * 64 + mt * 16 + h * 8 + g;
                int grow = mBase + lrow;
                float negc2 = -c2s[lrow];
                uint32_t mw = g_maskBits[(size_t)grow * NW + wordIdx];
                float bb = best[mt][h];
                int bi = bidx[mt][h];
#pragma unroll
                for (int nt = 0; nt < 4; nt++) {
                    int bpos = nt * 8 + tig * 2;
                    int lcol = wn * 32 + bpos;
                    float v0 = fmaxf(fmaf(-2.f, acc[mt][nt][h * 2 + 0], x2s[jt * 128 + lcol + 0]), negc2);
                    float v1 = fmaxf(fmaf(-2.f, acc[mt][nt][h * 2 + 1], x2s[jt * 128 + lcol + 1]), negc2);
                    if ((mw >> bpos) & 1u) v0 = FLTMAX;
                    if ((mw >> (bpos + 1)) & 1u) v1 = FLTMAX;
                    if (v0 < bb) { bb = v0; bi = jBase + lcol; }
                    if (v1 < bb) { bb = v1; bi = jBase + lcol + 1; }
                }
                best[mt][h] = bb;
                bidx[mt][h] = bi;
            }
    }

    // final reductions
#pragma unroll
    for (int mt = 0; mt < 4; mt++)
#pragma unroll
        for (int h = 0; h < 2; h++) {
            float bb = best[mt][h];
            int bi = bidx[mt][h];
#pragma unroll
            for (int o = 1; o < 4; o <<= 1) {
                float v = __shfl_down_sync(0xffffffffu, bb, o);
                int   i = __shfl_down_sync(0xffffffffu, bi, o);
                if (v < bb || (v == bb && i < bi)) { bb = v; bi = i; }
            }
            if (tig == 0) {
                int lrow = wm * 64 + mt * 16 + h * 8 + g;
                redV[lrow * 4 + wn] = bb;
                redI[lrow * 4 + wn] = bi;
            }
        }
    __syncthreads();

    if (tid < 128) {
        float bb = redV[tid * 4];
        int bi = redI[tid * 4];
#pragma unroll
        for (int w = 1; w < 4; w++) {
            float v = redV[tid * 4 + w];
            int   i = redI[tid * 4 + w];
            if (v < bb || (v == bb && i < bi)) { bb = v; bi = i; }
        }
        g_blockBest[(size_t)blockIdx.x * NN + mBase + tid] = bb;
        g_blockIdx [(size_t)blockIdx.x * NN + mBase + tid] = bi;
    }
}

__global__ __launch_bounds__(256) void argmin_combine() {
    int row = blockIdx.x * 256 + threadIdx.x;
    float best = g_blockBest[row];
    int bi = g_blockIdx[row];
#pragma unroll
    for (int nb = 1; nb < 16; nb++) {
        float v = g_blockBest[(size_t)nb * NN + row];
        int   i = g_blockIdx [(size_t)nb * NN + row];
        if (v < best || (v == best && i < bi)) { best = v; bi = i; }
    }
    g_negIdx[row] = bi;
}

// ---------------------------------------------------------------------------
// per-anchor triplet term (warp per anchor); reference adds EPS per component
// ---------------------------------------------------------------------------
__global__ __launch_bounds__(128) void loss_kernel(const float* __restrict__ X) {
    int a = blockIdx.x * 4 + (threadIdx.x >> 5);
    int lane = threadIdx.x & 31;
    float4 cv = reinterpret_cast<const float4*>(g_centers + (size_t)a * DD)[lane];
    float4 xv = reinterpret_cast<const float4*>(X + (size_t)a * DD)[lane];
    float4 nv = reinterpret_cast<const float4*>(X + (size_t)g_negIdx[a] * DD)[lane];
    const float EPS = 1e-6f;
    float t, sap = 0.f, san = 0.f;
    t = cv.x - xv.x + EPS; sap += t * t;
    t = cv.y - xv.y + EPS; sap += t * t;
    t = cv.z - xv.z + EPS; sap += t * t;
    t = cv.w - xv.w + EPS; sap += t * t;
    t = cv.x - nv.x + EPS; san += t * t;
    t = cv.y - nv.y + EPS; san += t * t;
    t = cv.z - nv.z + EPS; san += t * t;
    t = cv.w - nv.w + EPS; san += t * t;
#pragma unroll
    for (int o = 16; o; o >>= 1) {
        sap += __shfl_xor_sync(0xffffffffu, sap, o);
        san += __shfl_xor_sync(0xffffffffu, san, o);
    }
    if (lane == 0)
        g_loss[a] = fmaxf(sqrtf(sap) - sqrtf(san) + 0.3f, 0.f);
}

__global__ __launch_bounds__(1024) void reduce_kernel(float* out) {
    __shared__ float smr[1024];
    float s = 0.f;
    for (int i = threadIdx.x; i < NN; i += 1024) s += g_loss[i];
    smr[threadIdx.x] = s;
    __syncthreads();
    for (int o = 512; o; o >>= 1) {
        if (threadIdx.x < o) smr[threadIdx.x] += smr[threadIdx.x + o];
        __syncthreads();
    }
    if (threadIdx.x == 0) out[0] = smr[0] * (1.0f / NN);
}

// ---------------------------------------------------------------------------
extern "C" void kernel_launch(void* const* d_in, const int* in_sizes, int n_in,
                              void* d_out, int out_size) {
    const float* X;
    const int* S;
    if (in_sizes[0] == NN * DD) {
        X = (const float*)d_in[0];
        S = (const int*)d_in[1];
    } else {
        X = (const float*)d_in[1];
        S = (const int*)d_in[0];
    }

    cudaFuncSetAttribute(centers_mma, cudaFuncAttributeMaxDynamicSharedMemorySize, CEN_SM_TOTAL);
    cudaFuncSetAttribute(argmin_mma, cudaFuncAttributeMaxDynamicSharedMemorySize, ARG_SM_TOTAL);

    pack_kernel<<<NN / 8, 256>>>(S);
    prep_kernel<<<dim3(NN / 32, DD / 32), 256>>>(X);
    x2_kernel<<<NN / 8, 256>>>(X);
    centers_mma<<<dim3(64, 2), 256, CEN_SM_TOTAL>>>();
    centers_combine<<<NN / 4, 128>>>();
    argmin_mma<<<dim3(16, 64), 256, ARG_SM_TOTAL>>>();
    argmin_combine<<<NN / 256, 256>>>();
    loss_kernel<<<NN / 4, 128>>>(X);
    reduce_kernel<<<1, 1024>>>((float*)d_out);
}

// round 7
// speedup vs baseline: 7.4081x; 1.0003x over previous
#include <cuda_runtime.h>
#include <cuda_bf16.h>
#include <math.h>
#include <stdint.h>

#define NN 8192
#define DD 128
#define FLTMAX 3.402823466e38f
#define STRIDE 136   // padded bf16 row stride (272B): conflict-free LDSM rows
#define NW 256       // bitmask words per row (8192/32)

// ---------------- device-global scratch (no runtime allocation) -------------
__device__ float          g_centers[(size_t)NN * DD];
__device__ __nv_bfloat16  g_centersB[(size_t)NN * DD];
__device__ __nv_bfloat16  g_Xb [(size_t)NN * DD];   // X bf16 row-major [j][d]
__device__ __nv_bfloat16  g_XbT[(size_t)DD * NN];   // X^T bf16 [d][j]
__device__ uint32_t       g_maskBits[(size_t)NN * NW]; // packed mask bits
__device__ float          g_cntF[NN];
__device__ float          g_x2[NN];
__device__ float          g_c2[NN];
__device__ float          g_part[(size_t)2 * NN * DD];
__device__ float          g_blockBest[(size_t)16 * NN];
__device__ int            g_blockIdx [(size_t)16 * NN];
__device__ int            g_negIdx[NN];
__device__ float          g_loss[NN];

// ---------------- MMA / LDSM / cp.async helpers ------------------------------
__device__ __forceinline__ void mma16816(float c[4],
                                         uint32_t a0, uint32_t a1, uint32_t a2, uint32_t a3,
                                         uint32_t b0, uint32_t b1) {
    asm volatile(
        "mma.sync.aligned.m16n8k16.row.col.f32.bf16.bf16.f32 "
        "{%0,%1,%2,%3}, {%4,%5,%6,%7}, {%8,%9}, {%0,%1,%2,%3};"
        : "+f"(c[0]), "+f"(c[1]), "+f"(c[2]), "+f"(c[3])
        : "r"(a0), "r"(a1), "r"(a2), "r"(a3), "r"(b0), "r"(b1));
}

__device__ __forceinline__ void ldsm4(uint32_t r[4], uint32_t addr) {
    asm volatile("ldmatrix.sync.aligned.m8n8.x4.shared.b16 {%0,%1,%2,%3}, [%4];"
        : "=r"(r[0]), "=r"(r[1]), "=r"(r[2]), "=r"(r[3]) : "r"(addr));
}

__device__ __forceinline__ uint32_t smem_u32(const void* p) {
    uint32_t a;
    asm("{ .reg .u64 t; cvta.to.shared.u64 t, %1; cvt.u32.u64 %0, t; }" : "=r"(a) : "l"(p));
    return a;
}

#define CP_ASYNC16(dst, src) \
    asm volatile("cp.async.cg.shared.global [%0], [%1], 16;" :: "r"(dst), "l"(src))
#define CP_COMMIT() asm volatile("cp.async.commit_group;" ::: "memory")
#define CP_WAIT0()  asm volatile("cp.async.wait_group 0;" ::: "memory")

// two mask bits (i, i+1) -> packed bf16x2 {0|1, 0|1}
__device__ __forceinline__ uint32_t pack2(uint32_t m, int i) {
    return ((m >> i) & 1u) * 0x3F80u + ((m >> (i + 1)) & 1u) * 0x3F800000u;
}

// ---------------------------------------------------------------------------
// pack: similarity int32 -> bitmask + per-row count. warp per row.
// ---------------------------------------------------------------------------
__global__ __launch_bounds__(256) void pack_kernel(const int* __restrict__ S) {
    int row = blockIdx.x * 8 + (threadIdx.x >> 5);
    int lane = threadIdx.x & 31;
    const int* src = S + (size_t)row * NN;
    uint32_t* dst = g_maskBits + (size_t)row * NW;
    int cnt = 0;
#pragma unroll 4
    for (int it = 0; it < 64; it++) {
        int base = it * 128;
        uint32_t b0 = __ballot_sync(0xffffffffu, src[base + lane] != 0);
        uint32_t b1 = __ballot_sync(0xffffffffu, src[base + 32 + lane] != 0);
        uint32_t b2 = __ballot_sync(0xffffffffu, src[base + 64 + lane] != 0);
        uint32_t b3 = __ballot_sync(0xffffffffu, src[base + 96 + lane] != 0);
        if (lane == 0) {
            *reinterpret_cast<uint4*>(dst + it * 4) = make_uint4(b0, b1, b2, b3);
            cnt += __popc(b0) + __popc(b1) + __popc(b2) + __popc(b3);
        }
    }
    if (lane == 0) g_cntF[row] = (float)cnt;
}

// ---------------------------------------------------------------------------
// prep: Xb (bf16), XbT (bf16 transposed) via smem tile transpose
// ---------------------------------------------------------------------------
__global__ __launch_bounds__(256) void prep_kernel(const float* __restrict__ X) {
    __shared__ float tile[32][33];
    int tx = threadIdx.x & 31, ty = threadIdx.x >> 5;
    int j0 = blockIdx.x * 32, d0 = blockIdx.y * 32;
#pragma unroll
    for (int jr = ty; jr < 32; jr += 8) {
        float v = X[(size_t)(j0 + jr) * DD + d0 + tx];
        tile[jr][tx] = v;
        g_Xb[(size_t)(j0 + jr) * DD + d0 + tx] = __float2bfloat16_rn(v);
    }
    __syncthreads();
#pragma unroll
    for (int dr = ty; dr < 32; dr += 8)
        g_XbT[(size_t)(d0 + dr) * NN + j0 + tx] = __float2bfloat16_rn(tile[tx][dr]);
}

__global__ __launch_bounds__(256) void x2_kernel(const float* __restrict__ X) {
    int warp = blockIdx.x * 8 + (threadIdx.x >> 5);
    int lane = threadIdx.x & 31;
    float4 a = reinterpret_cast<const float4*>(X + (size_t)warp * DD)[lane];
    float s = a.x * a.x + a.y * a.y + a.z * a.z + a.w * a.w;
#pragma unroll
    for (int o = 16; o; o >>= 1) s += __shfl_xor_sync(0xffffffffu, s, o);
    if (lane == 0) g_x2[warp] = s;
}

// ---------------------------------------------------------------------------
// centers HMMA: part[128 rows, 128 dims] = mask_bf16 @ XbT over K-split 4096
// grid (64 mb, 2 split) = 128 CTAs, 512 threads (16 warps as 4x4).
// cp.async double-buffered B + mask words; A expanded in smem per iter.
// smem: A @0 (34816) | B0 @34816 | B1 @69632 | M0 @104448 (2KB) | M1 @106496
// ---------------------------------------------------------------------------
#define CEN_SM_B(buf)  (34816 + (buf) * 34816)
#define CEN_SM_M(buf)  (104448 + (buf) * 2048)
#define CEN_SM_TOTAL   108544

__global__ __launch_bounds__(512) void centers_mma() {
    extern __shared__ __align__(16) char sm[];
    const uint32_t smb = smem_u32(sm);
    __nv_bfloat16* As = reinterpret_cast<__nv_bfloat16*>(sm);

    const int tid = threadIdx.x;
    const int wid = tid >> 5, lane = tid & 31;
    const int wm = wid >> 2, wn = wid & 3;          // 4 x 4 warps
    const int rowBase = blockIdx.x * 128;
    const int kBase = blockIdx.y * 4096;

    const int lr = tid >> 2;          // row 0..127
    const int q  = tid & 3;           // 32-elem quarter

    // LDSM lane addressing
    const int l7 = lane & 7, lid8 = lane >> 3;
    uint32_t aoff[2], boffRel[2];
#pragma unroll
    for (int mt = 0; mt < 2; mt++)
        aoff[mt] = smb + (uint32_t)((wm * 32 + mt * 16 + (lid8 & 1) * 8 + l7) * STRIDE * 2 + (lid8 >> 1) * 16);
#pragma unroll
    for (int np = 0; np < 2; np++)
        boffRel[np] = (uint32_t)((wn * 32 + np * 16 + (lid8 >> 1) * 8 + l7) * STRIDE * 2 + (lid8 & 1) * 16);

    float acc[2][4][4];
#pragma unroll
    for (int mt = 0; mt < 2; mt++)
#pragma unroll
        for (int nt = 0; nt < 4; nt++)
#pragma unroll
            for (int qq = 0; qq < 4; qq++) acc[mt][nt][qq] = 0.f;

    // issue loads for iter 0
    {
        uint32_t bdst = smb + CEN_SM_B(0) + (uint32_t)(lr * STRIDE + q * 32) * 2;
        const __nv_bfloat16* bsrc = g_XbT + (size_t)lr * NN + kBase + q * 32;
#pragma unroll
        for (int u = 0; u < 4; u++) CP_ASYNC16(bdst + u * 16, bsrc + u * 8);
        if (tid < 128) {
            uint32_t mdst = smb + CEN_SM_M(0) + tid * 16;
            CP_ASYNC16(mdst, g_maskBits + (size_t)(rowBase + tid) * NW + (kBase >> 5));
        }
        CP_COMMIT();
    }

    for (int it = 0; it < 32; it++) {
        const int buf = it & 1;
        CP_WAIT0();
        __syncthreads();

        if (it + 1 < 32) {
            const int k0 = kBase + (it + 1) * 128;
            uint32_t bdst = smb + CEN_SM_B(buf ^ 1) + (uint32_t)(lr * STRIDE + q * 32) * 2;
            const __nv_bfloat16* bsrc = g_XbT + (size_t)lr * NN + k0 + q * 32;
#pragma unroll
            for (int u = 0; u < 4; u++) CP_ASYNC16(bdst + u * 16, bsrc + u * 8);
            if (tid < 128) {
                uint32_t mdst = smb + CEN_SM_M(buf ^ 1) + tid * 16;
                CP_ASYNC16(mdst, g_maskBits + (size_t)(rowBase + tid) * NW + (k0 >> 5));
            }
            CP_COMMIT();
        }

        // expand A tile: one 32-bit mask word per thread -> 32 bf16
        {
            uint32_t mword = reinterpret_cast<const uint32_t*>(sm + CEN_SM_M(buf))[tid];
            __nv_bfloat16* arow = As + lr * STRIDE + q * 32;
#pragma unroll
            for (int u = 0; u < 4; u++)
                *reinterpret_cast<uint4*>(arow + u * 8) =
                    make_uint4(pack2(mword, u * 8), pack2(mword, u * 8 + 2),
                               pack2(mword, u * 8 + 4), pack2(mword, u * 8 + 6));
        }
        __syncthreads();

        const uint32_t bbase = smb + CEN_SM_B(buf);
#pragma unroll
        for (int ks = 0; ks < 8; ks++) {
            const uint32_t kb = ks * 32;
            uint32_t a[2][4], b[2][4];
#pragma unroll
            for (int mt = 0; mt < 2; mt++) ldsm4(a[mt], aoff[mt] + kb);
#pragma unroll
            for (int np = 0; np < 2; np++) ldsm4(b[np], bbase + boffRel[np] + kb);
#pragma unroll
            for (int mt = 0; mt < 2; mt++)
#pragma unroll
                for (int nt = 0; nt < 4; nt++)
                    mma16816(acc[mt][nt], a[mt][0], a[mt][1], a[mt][2], a[mt][3],
                             b[nt >> 1][(nt & 1) * 2], b[nt >> 1][(nt & 1) * 2 + 1]);
        }
    }

    const int g = lane >> 2, tig = lane & 3;
#pragma unroll
    for (int mt = 0; mt < 2; mt++)
#pragma unroll
        for (int h = 0; h < 2; h++) {
            int grow = rowBase + wm * 32 + mt * 16 + h * 8 + g;
#pragma unroll
            for (int nt = 0; nt < 4; nt++) {
                int col = wn * 32 + nt * 8 + tig * 2;
                float2 v = make_float2(acc[mt][nt][h * 2], acc[mt][nt][h * 2 + 1]);
                *reinterpret_cast<float2*>(g_part + ((size_t)blockIdx.y * NN + grow) * DD + col) = v;
            }
        }
}

// ---------------------------------------------------------------------------
// centers combine: sum 2 split partials, /count, write fp32 + bf16 + c2
// ---------------------------------------------------------------------------
__global__ __launch_bounds__(128) void centers_combine() {
    int row = blockIdx.x * 4 + (threadIdx.x >> 5);
    int lane = threadIdx.x & 31;
    float inv = 1.0f / g_cntF[row];
    float4 p0 = reinterpret_cast<const float4*>(g_part + (size_t)row * DD)[lane];
    float4 p1 = reinterpret_cast<const float4*>(g_part + ((size_t)NN + row) * DD)[lane];
    float4 s = make_float4((p0.x + p1.x) * inv, (p0.y + p1.y) * inv,
                           (p0.z + p1.z) * inv, (p0.w + p1.w) * inv);
    reinterpret_cast<float4*>(g_centers + (size_t)row * DD)[lane] = s;
    __nv_bfloat162 lo = __floats2bfloat162_rn(s.x, s.y);
    __nv_bfloat162 hi = __floats2bfloat162_rn(s.z, s.w);
    uint2 packed = make_uint2(*reinterpret_cast<uint32_t*>(&lo), *reinterpret_cast<uint32_t*>(&hi));
    reinterpret_cast<uint2*>(g_centersB + (size_t)row * DD)[lane] = packed;
    float c2 = s.x * s.x + s.y * s.y + s.z * s.z + s.w * s.w;
#pragma unroll
    for (int o = 16; o; o >>= 1) c2 += __shfl_xor_sync(0xffffffffu, c2, o);
    if (lane == 0) g_c2[row] = c2;
}

// ---------------------------------------------------------------------------
// argmin HMMA: dot[128 rows, 128 j] = centersB @ Xb^T (K=128), fused argmin.
// grid (16 nb, 64 mb) = 1024 CTAs, 512 threads (16 warps as 4x4); each CTA
// loops 4 j-tiles with cp.async double-buffered B. Running best in registers.
// ---------------------------------------------------------------------------
#define ARG_SM_B(buf)  (34816 + (buf) * 34816)
#define ARG_SM_X2      104448
#define ARG_SM_C2      106496
#define ARG_SM_RV      107008
#define ARG_SM_RI      109056
#define ARG_SM_TOTAL   111104

__global__ __launch_bounds__(512) void argmin_mma() {
    extern __shared__ __align__(16) char sm[];
    const uint32_t smb = smem_u32(sm);
    float* x2s = reinterpret_cast<float*>(sm + ARG_SM_X2);
    float* c2s = reinterpret_cast<float*>(sm + ARG_SM_C2);
    float* redV = reinterpret_cast<float*>(sm + ARG_SM_RV);
    int*   redI = reinterpret_cast<int*>(sm + ARG_SM_RI);

    const int tid = threadIdx.x;
    const int wid = tid >> 5, lane = tid & 31;
    const int wm = wid >> 2, wn = wid & 3;
    const int g = lane >> 2, tig = lane & 3;
    const int mBase = blockIdx.y * 128;
    const int jBase0 = blockIdx.x * 512;

    const int lr = tid >> 2, q = tid & 3;

    // prologue loads: A tile, x2 (512 floats), c2 (128 floats), B tile jt=0
    {
        uint32_t adst = smb + (uint32_t)(lr * STRIDE + q * 32) * 2;
        const __nv_bfloat16* asrc = g_centersB + (size_t)(mBase + lr) * DD + q * 32;
#pragma unroll
        for (int u = 0; u < 4; u++) CP_ASYNC16(adst + u * 16, asrc + u * 8);
        uint32_t bdst = smb + ARG_SM_B(0) + (uint32_t)(lr * STRIDE + q * 32) * 2;
        const __nv_bfloat16* bsrc = g_Xb + (size_t)(jBase0 + lr) * DD + q * 32;
#pragma unroll
        for (int u = 0; u < 4; u++) CP_ASYNC16(bdst + u * 16, bsrc + u * 8);
        if (tid < 128) CP_ASYNC16(smb + ARG_SM_X2 + tid * 16, g_x2 + jBase0 + tid * 4);
        else if (tid < 160) CP_ASYNC16(smb + ARG_SM_C2 + (tid - 128) * 16, g_c2 + mBase + (tid - 128) * 4);
        CP_COMMIT();
    }

    const int l7 = lane & 7, lid8 = lane >> 3;
    uint32_t aoff[2], boffRel[2];
#pragma unroll
    for (int mt = 0; mt < 2; mt++)
        aoff[mt] = smb + (uint32_t)((wm * 32 + mt * 16 + (lid8 & 1) * 8 + l7) * STRIDE * 2 + (lid8 >> 1) * 16);
#pragma unroll
    for (int np = 0; np < 2; np++)
        boffRel[np] = (uint32_t)((wn * 32 + np * 16 + (lid8 >> 1) * 8 + l7) * STRIDE * 2 + (lid8 & 1) * 16);

    float best[2][2];
    int   bidx[2][2];
#pragma unroll
    for (int mt = 0; mt < 2; mt++)
#pragma unroll
        for (int h = 0; h < 2; h++) { best[mt][h] = FLTMAX; bidx[mt][h] = 0x7FFFFFFF; }

    for (int jt = 0; jt < 4; jt++) {
        const int buf = jt & 1;
        const int jBase = jBase0 + jt * 128;
        CP_WAIT0();
        __syncthreads();

        if (jt + 1 < 4) {
            uint32_t bdst = smb + ARG_SM_B(buf ^ 1) + (uint32_t)(lr * STRIDE + q * 32) * 2;
            const __nv_bfloat16* bsrc = g_Xb + (size_t)(jBase0 + (jt + 1) * 128 + lr) * DD + q * 32;
#pragma unroll
            for (int u = 0; u < 4; u++) CP_ASYNC16(bdst + u * 16, bsrc + u * 8);
            CP_COMMIT();
        }

        float acc[2][4][4];
#pragma unroll
        for (int mt = 0; mt < 2; mt++)
#pragma unroll
            for (int nt = 0; nt < 4; nt++)
#pragma unroll
                for (int qq = 0; qq < 4; qq++) acc[mt][nt][qq] = 0.f;

        const uint32_t bbase = smb + ARG_SM_B(buf);
#pragma unroll
        for (int ks = 0; ks < 8; ks++) {
            const uint32_t kb = ks * 32;
            uint32_t a[2][4], b[2][4];
#pragma unroll
            for (int mt = 0; mt < 2; mt++) ldsm4(a[mt], aoff[mt] + kb);
#pragma unroll
            for (int np = 0; np < 2; np++) ldsm4(b[np], bbase + boffRel[np] + kb);
#pragma unroll
            for (int mt = 0; mt < 2; mt++)
#pragma unroll
                for (int nt = 0; nt < 4; nt++)
                    mma16816(acc[mt][nt], a[mt][0], a[mt][1], a[mt][2], a[mt][3],
                             b[nt >> 1][(nt & 1) * 2], b[nt >> 1][(nt & 1) * 2 + 1]);
        }

        // fused argmin update
        const int wordIdx = (jBase >> 5) + wn;
#pragma unroll
        for (int mt = 0; mt < 2; mt++)
#pragma unroll
            for (int h = 0; h < 2; h++) {
                int lrow = wm * 32 + mt * 16 + h * 8 + g;
                int grow = mBase + lrow;
                float negc2 = -c2s[lrow];
                uint32_t mw = g_maskBits[(size_t)grow * NW + wordIdx];
                float bb = best[mt][h];
                int bi = bidx[mt][h];
#pragma unroll
                for (int nt = 0; nt < 4; nt++) {
                    int bpos = nt * 8 + tig * 2;
                    int lcol = wn * 32 + bpos;
                    float v0 = fmaxf(fmaf(-2.f, acc[mt][nt][h * 2 + 0], x2s[jt * 128 + lcol + 0]), negc2);
                    float v1 = fmaxf(fmaf(-2.f, acc[mt][nt][h * 2 + 1], x2s[jt * 128 + lcol + 1]), negc2);
                    if ((mw >> bpos) & 1u) v0 = FLTMAX;
                    if ((mw >> (bpos + 1)) & 1u) v1 = FLTMAX;
                    if (v0 < bb) { bb = v0; bi = jBase + lcol; }
                    if (v1 < bb) { bb = v1; bi = jBase + lcol + 1; }
                }
                best[mt][h] = bb;
                bidx[mt][h] = bi;
            }
    }

    // final reductions
#pragma unroll
    for (int mt = 0; mt < 2; mt++)
#pragma unroll
        for (int h = 0; h < 2; h++) {
            float bb = best[mt][h];
            int bi = bidx[mt][h];
#pragma unroll
            for (int o = 1; o < 4; o <<= 1) {
                float v = __shfl_down_sync(0xffffffffu, bb, o);
                int   i = __shfl_down_sync(0xffffffffu, bi, o);
                if (v < bb || (v == bb && i < bi)) { bb = v; bi = i; }
            }
            if (tig == 0) {
                int lrow = wm * 32 + mt * 16 + h * 8 + g;
                redV[lrow * 4 + wn] = bb;
                redI[lrow * 4 + wn] = bi;
            }
        }
    __syncthreads();

    if (tid < 128) {
        float bb = redV[tid * 4];
        int bi = redI[tid * 4];
#pragma unroll
        for (int w = 1; w < 4; w++) {
            float v = redV[tid * 4 + w];
            int   i = redI[tid * 4 + w];
            if (v < bb || (v == bb && i < bi)) { bb = v; bi = i; }
        }
        g_blockBest[(size_t)blockIdx.x * NN + mBase + tid] = bb;
        g_blockIdx [(size_t)blockIdx.x * NN + mBase + tid] = bi;
    }
}

__global__ __launch_bounds__(256) void argmin_combine() {
    int row = blockIdx.x * 256 + threadIdx.x;
    float best = g_blockBest[row];
    int bi = g_blockIdx[row];
#pragma unroll
    for (int nb = 1; nb < 16; nb++) {
        float v = g_blockBest[(size_t)nb * NN + row];
        int   i = g_blockIdx [(size_t)nb * NN + row];
        if (v < best || (v == best && i < bi)) { best = v; bi = i; }
    }
    g_negIdx[row] = bi;
}

// ---------------------------------------------------------------------------
// per-anchor triplet term (warp per anchor); reference adds EPS per component
// ---------------------------------------------------------------------------
__global__ __launch_bounds__(128) void loss_kernel(const float* __restrict__ X) {
    int a = blockIdx.x * 4 + (threadIdx.x >> 5);
    int lane = threadIdx.x & 31;
    float4 cv = reinterpret_cast<const float4*>(g_centers + (size_t)a * DD)[lane];
    float4 xv = reinterpret_cast<const float4*>(X + (size_t)a * DD)[lane];
    float4 nv = reinterpret_cast<const float4*>(X + (size_t)g_negIdx[a] * DD)[lane];
    const float EPS = 1e-6f;
    float t, sap = 0.f, san = 0.f;
    t = cv.x - xv.x + EPS; sap += t * t;
    t = cv.y - xv.y + EPS; sap += t * t;
    t = cv.z - xv.z + EPS; sap += t * t;
    t = cv.w - xv.w + EPS; sap += t * t;
    t = cv.x - nv.x + EPS; san += t * t;
    t = cv.y - nv.y + EPS; san += t * t;
    t = cv.z - nv.z + EPS; san += t * t;
    t = cv.w - nv.w + EPS; san += t * t;
#pragma unroll
    for (int o = 16; o; o >>= 1) {
        sap += __shfl_xor_sync(0xffffffffu, sap, o);
        san += __shfl_xor_sync(0xffffffffu, san, o);
    }
    if (lane == 0)
        g_loss[a] = fmaxf(sqrtf(sap) - sqrtf(san) + 0.3f, 0.f);
}

__global__ __launch_bounds__(1024) void reduce_kernel(float* out) {
    __shared__ float smr[1024];
    float s = 0.f;
    for (int i = threadIdx.x; i < NN; i += 1024) s += g_loss[i];
    smr[threadIdx.x] = s;
    __syncthreads();
    for (int o = 512; o; o >>= 1) {
        if (threadIdx.x < o) smr[threadIdx.x] += smr[threadIdx.x + o];
        __syncthreads();
    }
    if (threadIdx.x == 0) out[0] = smr[0] * (1.0f / NN);
}

// ---------------------------------------------------------------------------
extern "C" void kernel_launch(void* const* d_in, const int* in_sizes, int n_in,
                              void* d_out, int out_size) {
    const float* X;
    const int* S;
    if (in_sizes[0] == NN * DD) {
        X = (const float*)d_in[0];
        S = (const int*)d_in[1];
    } else {
        X = (const float*)d_in[1];
        S = (const int*)d_in[0];
    }

    cudaFuncSetAttribute(centers_mma, cudaFuncAttributeMaxDynamicSharedMemorySize, CEN_SM_TOTAL);
    cudaFuncSetAttribute(argmin_mma, cudaFuncAttributeMaxDynamicSharedMemorySize, ARG_SM_TOTAL);

    pack_kernel<<<NN / 8, 256>>>(S);
    prep_kernel<<<dim3(NN / 32, DD / 32), 256>>>(X);
    x2_kernel<<<NN / 8, 256>>>(X);
    centers_mma<<<dim3(64, 2), 512, CEN_SM_TOTAL>>>();
    centers_combine<<<NN / 4, 128>>>();
    argmin_mma<<<dim3(16, 64), 512, ARG_SM_TOTAL>>>();
    argmin_combine<<<NN / 256, 256>>>();
    loss_kernel<<<NN / 4, 128>>>(X);
    reduce_kernel<<<1, 1024>>>((float*)d_out);
}